// round 1
// baseline (speedup 1.0000x reference)
#include <cuda_runtime.h>
#include <math.h>

// Problem: batch-hard triplet loss. B=8192, D=256 (kernel reads sizes at runtime).
#define MAX_B 8192
#define MARGIN 0.3f

__device__ float  g_norms[MAX_B];
__device__ int    g_labels[MAX_B];
__device__ float2 g_pl[MAX_B];   // (per-anchor loss, valid flag)

// ---------------------------------------------------------------------------
// Labels may arrive as int32 (JAX x64 disabled) or int64. Detect: view the
// buffer as int32; if the odd words of the first 32 pairs are all zero, it's
// little-endian int64 (values in [0,512) -> high word 0). Probability of a
// false positive with int32 labels: (1/512)^32 ~ 0.
// ---------------------------------------------------------------------------
__global__ void labels_kernel(const void* lab, int B) {
    __shared__ int is64;
    const int* li = (const int*)lab;
    if (threadIdx.x == 0) {
        int all0 = 1;
        #pragma unroll
        for (int i = 0; i < 32; i++)
            if (li[2 * i + 1] != 0) all0 = 0;
        is64 = all0;
    }
    __syncthreads();
    if (is64) {
        const long long* l8 = (const long long*)lab;
        for (int i = threadIdx.x; i < B; i += blockDim.x)
            g_labels[i] = (int)l8[i];
    } else {
        for (int i = threadIdx.x; i < B; i += blockDim.x)
            g_labels[i] = li[i];
    }
}

// ---------------------------------------------------------------------------
// Row norms: one warp per row, float4 loads, shfl reduce.
// ---------------------------------------------------------------------------
__global__ void norms_kernel(const float* __restrict__ E, int B, int D) {
    int warp = threadIdx.x >> 5, lane = threadIdx.x & 31;
    int row = blockIdx.x * 8 + warp;
    if (row >= B) return;
    const float4* e4 = (const float4*)(E + (size_t)row * D);
    float s = 0.f;
    for (int c = lane; c < (D >> 2); c += 32) {
        float4 v = e4[c];
        s += v.x * v.x + v.y * v.y + v.z * v.z + v.w * v.w;
    }
    #pragma unroll
    for (int o = 16; o; o >>= 1) s += __shfl_xor_sync(0xFFFFFFFFu, s, o);
    if (lane == 0) g_norms[row] = s;
}

// ---------------------------------------------------------------------------
// Fused Gram + batch-hard mining.
// Tile: 64 rows x 64 cols per block, 256 threads, 4x4 micro-tile, KC=32.
// dist^2(i,j) = clip(n_i + n_j - 2*dot, 0)
//   same label, j!=i  -> maxpos candidate
//   diff label        -> minneg candidate
// After the column sweep, reduce across the 16 threads sharing each row
// (shfl within a 16-lane group), and emit per-anchor loss + valid flag.
// Assumes B % 64 == 0 and D % 32 == 0 (8192, 256).
// ---------------------------------------------------------------------------
#define TM 64
#define TN 64
#define KC 32

__global__ __launch_bounds__(256, 1)
void mine_kernel(const float* __restrict__ E, int B, int D) {
    __shared__ float As[KC][TM + 4];
    __shared__ float Bs[KC][TN + 4];
    __shared__ int   lblB[TN];
    __shared__ float nrmB[TN];

    const int tid = threadIdx.x;
    const int tx = tid & 15;        // 16 col-groups
    const int ty = tid >> 4;        // 16 row-groups
    const int row0 = blockIdx.x * TM;

    // load-phase mapping: thread covers row (tid>>2), k-segment (tid&3)*8
    const int lr = tid >> 2;
    const int lk = (tid & 3) * 8;

    int   myrow[4], mylbl[4];
    float mynorm[4];
    #pragma unroll
    for (int r = 0; r < 4; r++) {
        myrow[r]  = row0 + ty * 4 + r;
        mylbl[r]  = g_labels[myrow[r]];
        mynorm[r] = g_norms[myrow[r]];
    }

    float maxpos[4] = {-1.f, -1.f, -1.f, -1.f};
    float minneg[4] = {3.4e38f, 3.4e38f, 3.4e38f, 3.4e38f};

    for (int jt = 0; jt < B; jt += TN) {
        __syncthreads();  // protect lblB/nrmB from previous iteration's readers
        if (tid < TN) {
            lblB[tid] = g_labels[jt + tid];
            nrmB[tid] = g_norms[jt + tid];
        }

        float acc[4][4];
        #pragma unroll
        for (int r = 0; r < 4; r++)
            #pragma unroll
            for (int c = 0; c < 4; c++) acc[r][c] = 0.f;

        for (int kt = 0; kt < D; kt += KC) {
            // stage A tile (rows row0..row0+63) and B tile (rows jt..jt+63),
            // transposed to [k][m] layout for vector LDS in the inner loop
            {
                const float* pa = E + (size_t)(row0 + lr) * D + kt + lk;
                const float* pb = E + (size_t)(jt   + lr) * D + kt + lk;
                float4 a0 = *(const float4*)(pa);
                float4 a1 = *(const float4*)(pa + 4);
                float4 b0 = *(const float4*)(pb);
                float4 b1 = *(const float4*)(pb + 4);
                As[lk + 0][lr] = a0.x; As[lk + 1][lr] = a0.y;
                As[lk + 2][lr] = a0.z; As[lk + 3][lr] = a0.w;
                As[lk + 4][lr] = a1.x; As[lk + 5][lr] = a1.y;
                As[lk + 6][lr] = a1.z; As[lk + 7][lr] = a1.w;
                Bs[lk + 0][lr] = b0.x; Bs[lk + 1][lr] = b0.y;
                Bs[lk + 2][lr] = b0.z; Bs[lk + 3][lr] = b0.w;
                Bs[lk + 4][lr] = b1.x; Bs[lk + 5][lr] = b1.y;
                Bs[lk + 6][lr] = b1.z; Bs[lk + 7][lr] = b1.w;
            }
            __syncthreads();

            #pragma unroll
            for (int k = 0; k < KC; k++) {
                float4 a = *(const float4*)&As[k][ty * 4];
                float4 b = *(const float4*)&Bs[k][tx * 4];
                acc[0][0] += a.x * b.x; acc[0][1] += a.x * b.y;
                acc[0][2] += a.x * b.z; acc[0][3] += a.x * b.w;
                acc[1][0] += a.y * b.x; acc[1][1] += a.y * b.y;
                acc[1][2] += a.y * b.z; acc[1][3] += a.y * b.w;
                acc[2][0] += a.z * b.x; acc[2][1] += a.z * b.y;
                acc[2][2] += a.z * b.z; acc[2][3] += a.z * b.w;
                acc[3][0] += a.w * b.x; acc[3][1] += a.w * b.y;
                acc[3][2] += a.w * b.z; acc[3][3] += a.w * b.w;
            }
            __syncthreads();
        }

        // fold this 64-col tile into the running max/min
        #pragma unroll
        for (int c = 0; c < 4; c++) {
            int   j  = jt + tx * 4 + c;
            int   lj = lblB[tx * 4 + c];
            float nj = nrmB[tx * 4 + c];
            #pragma unroll
            for (int r = 0; r < 4; r++) {
                if (j == myrow[r]) continue;
                float d = fmaxf(mynorm[r] + nj - 2.f * acc[r][c], 0.f);
                if (lj == mylbl[r]) maxpos[r] = fmaxf(maxpos[r], d);
                else                minneg[r] = fminf(minneg[r], d);
            }
        }
    }

    // reduce across the 16 threads (tx=0..15) that share each row.
    // tid = ty*16+tx -> lane = (ty&1)*16 + tx, so xor-shuffles of 1,2,4,8
    // stay inside the 16-lane group.
    #pragma unroll
    for (int o = 8; o; o >>= 1) {
        #pragma unroll
        for (int r = 0; r < 4; r++) {
            maxpos[r] = fmaxf(maxpos[r], __shfl_xor_sync(0xFFFFFFFFu, maxpos[r], o));
            minneg[r] = fminf(minneg[r], __shfl_xor_sync(0xFFFFFFFFu, minneg[r], o));
        }
    }

    if (tx == 0) {
        #pragma unroll
        for (int r = 0; r < 4; r++) {
            float valid = (maxpos[r] >= 0.f && minneg[r] < 3.0e38f) ? 1.f : 0.f;
            float per = 0.f;
            if (valid > 0.f)
                per = fmaxf(sqrtf(maxpos[r]) - sqrtf(minneg[r]) + MARGIN, 0.f);
            g_pl[myrow[r]] = make_float2(per, valid);
        }
    }
}

// ---------------------------------------------------------------------------
// Deterministic single-block reduction to the scalar loss.
// ---------------------------------------------------------------------------
__global__ void finalize_kernel(float* out, int B) {
    __shared__ float ss[32], sv[32];
    int tid = threadIdx.x;
    float s = 0.f, v = 0.f;
    for (int i = tid; i < B; i += blockDim.x) {
        float2 p = g_pl[i];
        s += p.x; v += p.y;
    }
    #pragma unroll
    for (int o = 16; o; o >>= 1) {
        s += __shfl_xor_sync(0xFFFFFFFFu, s, o);
        v += __shfl_xor_sync(0xFFFFFFFFu, v, o);
    }
    int warp = tid >> 5, lane = tid & 31;
    if (lane == 0) { ss[warp] = s; sv[warp] = v; }
    __syncthreads();
    if (warp == 0) {
        int nw = blockDim.x >> 5;
        s = (lane < nw) ? ss[lane] : 0.f;
        v = (lane < nw) ? sv[lane] : 0.f;
        #pragma unroll
        for (int o = 16; o; o >>= 1) {
            s += __shfl_xor_sync(0xFFFFFFFFu, s, o);
            v += __shfl_xor_sync(0xFFFFFFFFu, v, o);
        }
        if (lane == 0) out[0] = (v > 0.f) ? (s / fmaxf(v, 1.f)) : 0.f;
    }
}

extern "C" void kernel_launch(void* const* d_in, const int* in_sizes, int n_in,
                              void* d_out, int out_size) {
    const float* E   = (const float*)d_in[0];
    const void*  lab = d_in[1];
    int B = in_sizes[1];              // labels element count
    int D = in_sizes[0] / B;          // 256

    labels_kernel<<<1, 256>>>(lab, B);
    norms_kernel<<<(B + 7) / 8, 256>>>(E, B, D);
    mine_kernel<<<B / TM, 256>>>(E, B, D);
    finalize_kernel<<<1, 1024>>>((float*)d_out, B);
}

// round 4
// speedup vs baseline: 7.9029x; 7.9029x over previous
#include <cuda_runtime.h>
#include <cuda_bf16.h>
#include <math.h>
#include <stdint.h>

#define Bsz    8192
#define Ddim   256
#define MARGIN 0.3f
#define NT     64            // number of 128-row tiles
#define NTILES (NT * (NT + 1) / 2)   // 2080 upper-triangle tile pairs

// ---- dynamic SMEM layout ----
// 2 k-chunk buffers x 4 arrays (Ahi,Alo,Bhi,Blo) x [128 rows][128 bytes] = 131072
// njlR (128 float2) + njlC (128 float2)                                  =   2048
#define SM_BUF(b)      ((b) * 65536)
#define SM_ARR(b, a)   (SM_BUF(b) + (a) * 16384)
#define SM_NJR         131072
#define SM_NJC         132096
#define SMEM_TOTAL     133120

// ---- device globals ----
__device__ float         g_norms[Bsz];
__device__ int           g_labels[Bsz];
__device__ float2        g_njl[Bsz];             // {norm, label bits}
__device__ __nv_bfloat16 g_hi[Bsz * Ddim];
__device__ __nv_bfloat16 g_lo[Bsz * Ddim];
__device__ unsigned int  g_vpos[Bsz];            // encoded max(nj - 2dot) over positives
__device__ unsigned int  g_vneg[Bsz];            // encoded min(nj - 2dot) over negatives

// monotone float<->uint encoding (order-preserving)
__device__ __forceinline__ unsigned int enc(float f) {
    unsigned int u = __float_as_uint(f);
    return (u & 0x80000000u) ? ~u : (u | 0x80000000u);
}
__device__ __forceinline__ float dec(unsigned int u) {
    return (u & 0x80000000u) ? __uint_as_float(u ^ 0x80000000u) : __uint_as_float(~u);
}

__device__ __forceinline__ uint32_t smem_u32(const void* p) {
    uint32_t a;
    asm("{ .reg .u64 t; cvta.to.shared.u64 t, %1; cvt.u32.u64 %0, t; }" : "=r"(a) : "l"(p));
    return a;
}
__device__ __forceinline__ void cp_async16(uint32_t dst, const void* src) {
    asm volatile("cp.async.cg.shared.global [%0], [%1], 16;" :: "r"(dst), "l"(src) : "memory");
}
__device__ __forceinline__ void cp_commit() {
    asm volatile("cp.async.commit_group;" ::: "memory");
}
template <int N>
__device__ __forceinline__ void cp_wait() {
    asm volatile("cp.async.wait_group %0;" :: "n"(N) : "memory");
}
__device__ __forceinline__ void ldm_x4(uint32_t r[4], uint32_t addr) {
    asm volatile("ldmatrix.sync.aligned.m8n8.x4.shared.b16 {%0,%1,%2,%3}, [%4];"
                 : "=r"(r[0]), "=r"(r[1]), "=r"(r[2]), "=r"(r[3]) : "r"(addr));
}
__device__ __forceinline__ void mma16816(float d[4], const uint32_t a[4],
                                         uint32_t b0, uint32_t b1) {
    asm volatile(
        "mma.sync.aligned.m16n8k16.row.col.f32.bf16.bf16.f32 "
        "{%0,%1,%2,%3},{%4,%5,%6,%7},{%8,%9},{%0,%1,%2,%3};"
        : "+f"(d[0]), "+f"(d[1]), "+f"(d[2]), "+f"(d[3])
        : "r"(a[0]), "r"(a[1]), "r"(a[2]), "r"(a[3]), "r"(b0), "r"(b1));
}
__device__ __forceinline__ uint32_t swz(uint32_t off) {
    return off ^ ((off >> 3) & 0x70);
}

// ---------------- prep kernels ----------------
__global__ void labels_kernel(const void* lab, int B) {
    __shared__ int is64;
    const int* li = (const int*)lab;
    if (threadIdx.x == 0) {
        int all0 = 1;
        #pragma unroll
        for (int i = 0; i < 32; i++)
            if (li[2 * i + 1] != 0) all0 = 0;
        is64 = all0;
    }
    __syncthreads();
    if (is64) {
        const long long* l8 = (const long long*)lab;
        for (int i = threadIdx.x; i < B; i += blockDim.x) g_labels[i] = (int)l8[i];
    } else {
        for (int i = threadIdx.x; i < B; i += blockDim.x) g_labels[i] = li[i];
    }
}

__global__ void pack_kernel(const float* __restrict__ E) {
    int i = blockIdx.x * blockDim.x + threadIdx.x;
    float a = E[i];
    __nv_bfloat16 h = __float2bfloat16(a);
    g_hi[i] = h;
    g_lo[i] = __float2bfloat16(a - __bfloat162float(h));
}

__global__ void norms_kernel(const float* __restrict__ E) {
    int warp = threadIdx.x >> 5, lane = threadIdx.x & 31;
    int row = blockIdx.x * 8 + warp;
    if (threadIdx.x < 8) {
        int idx = blockIdx.x * 8 + threadIdx.x;
        g_vpos[idx] = 0u;
        g_vneg[idx] = 0xFFFFFFFFu;
    }
    if (row >= Bsz) return;
    const float4* e4 = (const float4*)(E + (size_t)row * Ddim);
    float s = 0.f;
    for (int c = lane; c < (Ddim >> 2); c += 32) {
        float4 v = e4[c];
        s += v.x * v.x + v.y * v.y + v.z * v.z + v.w * v.w;
    }
    #pragma unroll
    for (int o = 16; o; o >>= 1) s += __shfl_xor_sync(0xFFFFFFFFu, s, o);
    if (lane == 0) {
        g_norms[row] = s;
        g_njl[row] = make_float2(s, __int_as_float(g_labels[row]));
    }
}

// ---------------- main fused kernel ----------------
// One CTA per upper-triangle tile pair (it <= jt). 512 threads, 16 warps in a
// 4x4 grid; each warp computes a 32x32 block (2 row-atoms x 4 col-atoms of
// m16n8k16). 3 bf16 passes accumulate full-precision dot. Epilogue folds the
// tile both row-wise (anchors = it rows) and col-wise (anchors = jt rows) and
// merges via monotone-encoded atomic max/min.
__global__ __launch_bounds__(512, 1) void mine_kernel() {
    extern __shared__ char smem[];
    const uint32_t sb = smem_u32(smem);
    const int tid  = threadIdx.x;
    const int wid  = tid >> 5;
    const int lane = tid & 31;
    const int wr   = wid & 3;          // 32-row block
    const int wc   = wid >> 2;         // 32-col block

    // map blockIdx -> (it, jt), it <= jt
    int it = 0, rem = blockIdx.x;
    while (rem >= NT - it) { rem -= NT - it; it++; }
    const int jt   = it + rem;
    const int row0 = it * 128;
    const int col0 = jt * 128;

    // stage norms+labels for both tile edges
    if (tid < 128)                ((float2*)(smem + SM_NJR))[tid]       = g_njl[row0 + tid];
    else if (tid < 256)           ((float2*)(smem + SM_NJC))[tid - 128] = g_njl[col0 + tid - 128];

    // ---- cp.async loader for one 64-wide k-chunk into buffer b ----
    // 4 arrays x 1024 16B-segments; 8 segments per thread.
    auto issue_chunk = [&](int kc, int b) {
        #pragma unroll
        for (int i = 0; i < 8; i++) {
            int u   = i * 512 + tid;
            int arr = u >> 10;
            int s   = u & 1023;
            int r   = s >> 3;
            int q   = s & 7;
            const __nv_bfloat16* base = (arr & 1) ? g_lo : g_hi;
            int grow = ((arr >> 1) ? col0 : row0) + r;
            const void* src = base + (size_t)grow * Ddim + kc * 64 + q * 8;
            uint32_t dst = sb + SM_ARR(b, arr) + swz((uint32_t)(r * 128 + q * 16));
            cp_async16(dst, src);
        }
        cp_commit();
    };

    float acc[2][4][4];
    #pragma unroll
    for (int ar = 0; ar < 2; ar++)
        #pragma unroll
        for (int ac = 0; ac < 4; ac++)
            #pragma unroll
            for (int e = 0; e < 4; e++) acc[ar][ac][e] = 0.f;

    const int Rb = wr * 32;
    const int Cb = wc * 32;
    const int seg   = lane >> 3;
    const int l7    = lane & 7;
    // A ldmatrix lane address pieces: rows (seg&1)*8+l7, k-halves (seg>>1)*16
    const int a_radd = (seg & 1) * 8 + l7;
    const int a_koff = (seg >> 1) * 16;
    // B ldmatrix: rows (cols of tile) (seg>>1)*8+l7, k-halves (seg&1)*16
    const int b_radd = (seg >> 1) * 8 + l7;
    const int b_koff = (seg & 1) * 16;

    issue_chunk(0, 0);
    #pragma unroll
    for (int kc = 0; kc < 4; kc++) {
        const int b = kc & 1;
        if (kc < 3) { issue_chunk(kc + 1, b ^ 1); cp_wait<1>(); }
        else        { cp_wait<0>(); }
        __syncthreads();

        #pragma unroll
        for (int ks = 0; ks < 4; ks++) {
            uint32_t ah[2][4], al[2][4], bh[2][4], bl[2][4];
            #pragma unroll
            for (int ar = 0; ar < 2; ar++) {
                uint32_t off = swz((uint32_t)((Rb + ar * 16 + a_radd) * 128 + ks * 32 + a_koff));
                ldm_x4(ah[ar], sb + SM_ARR(b, 0) + off);
                ldm_x4(al[ar], sb + SM_ARR(b, 1) + off);
            }
            #pragma unroll
            for (int cp = 0; cp < 2; cp++) {
                uint32_t off = swz((uint32_t)((Cb + cp * 16 + b_radd) * 128 + ks * 32 + b_koff));
                ldm_x4(bh[cp], sb + SM_ARR(b, 2) + off);
                ldm_x4(bl[cp], sb + SM_ARR(b, 3) + off);
            }
            #pragma unroll
            for (int ar = 0; ar < 2; ar++)
                #pragma unroll
                for (int ac = 0; ac < 4; ac++) {
                    const int cp = ac >> 1, sel = (ac & 1) * 2;
                    mma16816(acc[ar][ac], ah[ar], bh[cp][sel], bh[cp][sel + 1]);
                    mma16816(acc[ar][ac], ah[ar], bl[cp][sel], bl[cp][sel + 1]);
                    mma16816(acc[ar][ac], al[ar], bh[cp][sel], bh[cp][sel + 1]);
                }
        }
        __syncthreads();
    }

    // ---- epilogue: dual-direction batch-hard fold ----
    const int g  = lane >> 2;
    const int qp = lane & 3;

    int   rowG[4]; float nR[4]; int lR[4];
    int   colG[8]; float nC[8]; int lC[8];
    const float2* njr = (const float2*)(smem + SM_NJR);
    const float2* njc = (const float2*)(smem + SM_NJC);
    #pragma unroll
    for (int ar = 0; ar < 2; ar++)
        #pragma unroll
        for (int h = 0; h < 2; h++) {
            int lr = Rb + ar * 16 + g + h * 8;
            int k = ar * 2 + h;
            rowG[k] = row0 + lr;
            nR[k] = njr[lr].x; lR[k] = __float_as_int(njr[lr].y);
        }
    #pragma unroll
    for (int ac = 0; ac < 4; ac++)
        #pragma unroll
        for (int p = 0; p < 2; p++) {
            int lc = Cb + ac * 8 + qp * 2 + p;
            int k = ac * 2 + p;
            colG[k] = col0 + lc;
            nC[k] = njc[lc].x; lC[k] = __float_as_int(njc[lc].y);
        }

    float rp[4], rn[4], cpx[8], cn[8];
    #pragma unroll
    for (int k = 0; k < 4; k++) { rp[k] = -1e30f; rn[k] = 1e30f; }
    #pragma unroll
    for (int k = 0; k < 8; k++) { cpx[k] = -1e30f; cn[k] = 1e30f; }

    #pragma unroll
    for (int ar = 0; ar < 2; ar++)
        #pragma unroll
        for (int ac = 0; ac < 4; ac++)
            #pragma unroll
            for (int e = 0; e < 4; e++) {
                const int ri = ar * 2 + (e >> 1);
                const int ci = ac * 2 + (e & 1);
                const float w  = -2.f * acc[ar][ac][e];
                const float vr = w + nC[ci];   // row-anchor candidate
                const float vc = w + nR[ri];   // col-anchor candidate
                if (lR[ri] == lC[ci]) {
                    if (rowG[ri] != colG[ci]) {
                        rp[ri]  = fmaxf(rp[ri], vr);
                        cpx[ci] = fmaxf(cpx[ci], vc);
                    }
                } else {
                    rn[ri] = fminf(rn[ri], vr);
                    cn[ci] = fminf(cn[ci], vc);
                }
            }

    // fold rows across the 4 lanes of each quad (same g, varying qp)
    #pragma unroll
    for (int o = 1; o <= 2; o <<= 1)
        #pragma unroll
        for (int k = 0; k < 4; k++) {
            rp[k] = fmaxf(rp[k], __shfl_xor_sync(0xFFFFFFFFu, rp[k], o));
            rn[k] = fminf(rn[k], __shfl_xor_sync(0xFFFFFFFFu, rn[k], o));
        }
    // fold cols across the 8 lanes with same qp (varying g)
    #pragma unroll
    for (int o = 4; o <= 16; o <<= 1)
        #pragma unroll
        for (int k = 0; k < 8; k++) {
            cpx[k] = fmaxf(cpx[k], __shfl_xor_sync(0xFFFFFFFFu, cpx[k], o));
            cn[k]  = fminf(cn[k],  __shfl_xor_sync(0xFFFFFFFFu, cn[k], o));
        }

    if (qp == 0) {
        #pragma unroll
        for (int k = 0; k < 4; k++) {
            if (rp[k] > -1e29f) atomicMax(&g_vpos[rowG[k]], enc(rp[k]));
            if (rn[k] <  1e29f) atomicMin(&g_vneg[rowG[k]], enc(rn[k]));
        }
    }
    if (g == 0) {
        #pragma unroll
        for (int k = 0; k < 8; k++) {
            if (cpx[k] > -1e29f) atomicMax(&g_vpos[colG[k]], enc(cpx[k]));
            if (cn[k]  <  1e29f) atomicMin(&g_vneg[colG[k]], enc(cn[k]));
        }
    }
}

// ---------------- finalize ----------------
__global__ void finalize_kernel(float* out) {
    __shared__ float ss[32], sv[32];
    int tid = threadIdx.x;
    float s = 0.f, v = 0.f;
    for (int i = tid; i < Bsz; i += blockDim.x) {
        float vp = dec(g_vpos[i]);   // NaN if never touched
        float vn = dec(g_vneg[i]);
        if (vp > -1e29f && vn < 1e29f) {
            float ni = g_norms[i];
            float dp = sqrtf(fmaxf(vp + ni, 0.f));
            float dn = sqrtf(fmaxf(vn + ni, 0.f));
            s += fmaxf(dp - dn + MARGIN, 0.f);
            v += 1.f;
        }
    }
    #pragma unroll
    for (int o = 16; o; o >>= 1) {
        s += __shfl_xor_sync(0xFFFFFFFFu, s, o);
        v += __shfl_xor_sync(0xFFFFFFFFu, v, o);
    }
    int warp = tid >> 5, lane = tid & 31;
    if (lane == 0) { ss[warp] = s; sv[warp] = v; }
    __syncthreads();
    if (warp == 0) {
        int nw = blockDim.x >> 5;
        s = (lane < nw) ? ss[lane] : 0.f;
        v = (lane < nw) ? sv[lane] : 0.f;
        #pragma unroll
        for (int o = 16; o; o >>= 1) {
            s += __shfl_xor_sync(0xFFFFFFFFu, s, o);
            v += __shfl_xor_sync(0xFFFFFFFFu, v, o);
        }
        if (lane == 0) out[0] = (v > 0.f) ? (s / fmaxf(v, 1.f)) : 0.f;
    }
}

extern "C" void kernel_launch(void* const* d_in, const int* in_sizes, int n_in,
                              void* d_out, int out_size) {
    const float* E   = (const float*)d_in[0];
    const void*  lab = d_in[1];
    int B = in_sizes[1];

    cudaFuncSetAttribute(mine_kernel, cudaFuncAttributeMaxDynamicSharedMemorySize, SMEM_TOTAL);

    labels_kernel<<<1, 256>>>(lab, B);
    pack_kernel<<<(Bsz * Ddim) / 1024, 1024>>>(E);
    norms_kernel<<<Bsz / 8, 256>>>(E);
    mine_kernel<<<NTILES, 512, SMEM_TOTAL>>>();
    finalize_kernel<<<1, 1024>>>((float*)d_out);
}

// round 5
// speedup vs baseline: 8.0061x; 1.0131x over previous
#include <cuda_runtime.h>
#include <cuda_bf16.h>
#include <math.h>
#include <stdint.h>

#define Bsz    8192
#define Ddim   256
#define MARGIN 0.3f
#define NT     64
#define NTILES (NT * (NT + 1) / 2)   // 2080

// ---- dynamic SMEM layout ----
#define SM_BUF(b)      ((b) * 65536)
#define SM_ARR(b, a)   (SM_BUF(b) + (a) * 16384)
#define SM_NJR         131072
#define SM_NJC         132096
#define SMEM_TOTAL     133120

// ---- device globals ----
__device__ float         g_norms[Bsz];
__device__ int           g_labels[Bsz];
__device__ float2        g_njl[Bsz];
__device__ __nv_bfloat16 g_hi[Bsz * Ddim];
__device__ __nv_bfloat16 g_lo[Bsz * Ddim];
__device__ unsigned int  g_vpos[Bsz];
__device__ unsigned int  g_vneg[Bsz];

__device__ __forceinline__ unsigned int enc(float f) {
    unsigned int u = __float_as_uint(f);
    return (u & 0x80000000u) ? ~u : (u | 0x80000000u);
}
__device__ __forceinline__ float dec(unsigned int u) {
    return (u & 0x80000000u) ? __uint_as_float(u ^ 0x80000000u) : __uint_as_float(~u);
}
__device__ __forceinline__ uint32_t smem_u32(const void* p) {
    uint32_t a;
    asm("{ .reg .u64 t; cvta.to.shared.u64 t, %1; cvt.u32.u64 %0, t; }" : "=r"(a) : "l"(p));
    return a;
}
__device__ __forceinline__ void cp_async16(uint32_t dst, const void* src) {
    asm volatile("cp.async.cg.shared.global [%0], [%1], 16;" :: "r"(dst), "l"(src) : "memory");
}
__device__ __forceinline__ void cp_commit() {
    asm volatile("cp.async.commit_group;" ::: "memory");
}
template <int N>
__device__ __forceinline__ void cp_wait() {
    asm volatile("cp.async.wait_group %0;" :: "n"(N) : "memory");
}
__device__ __forceinline__ void ldm_x4(uint32_t r[4], uint32_t addr) {
    asm volatile("ldmatrix.sync.aligned.m8n8.x4.shared.b16 {%0,%1,%2,%3}, [%4];"
                 : "=r"(r[0]), "=r"(r[1]), "=r"(r[2]), "=r"(r[3]) : "r"(addr));
}
__device__ __forceinline__ void mma16816(float d[4], const uint32_t a[4],
                                         uint32_t b0, uint32_t b1) {
    asm volatile(
        "mma.sync.aligned.m16n8k16.row.col.f32.bf16.bf16.f32 "
        "{%0,%1,%2,%3},{%4,%5,%6,%7},{%8,%9},{%0,%1,%2,%3};"
        : "+f"(d[0]), "+f"(d[1]), "+f"(d[2]), "+f"(d[3])
        : "r"(a[0]), "r"(a[1]), "r"(a[2]), "r"(a[3]), "r"(b0), "r"(b1));
}
__device__ __forceinline__ uint32_t swz(uint32_t off) {
    return off ^ ((off >> 3) & 0x70);
}

// ---------------- prep ----------------
__global__ void labels_kernel(const void* lab, int B) {
    __shared__ int is64;
    const int* li = (const int*)lab;
    if (threadIdx.x == 0) {
        int all0 = 1;
        #pragma unroll
        for (int i = 0; i < 32; i++)
            if (li[2 * i + 1] != 0) all0 = 0;
        is64 = all0;
    }
    __syncthreads();
    if (is64) {
        const long long* l8 = (const long long*)lab;
        for (int i = threadIdx.x; i < B; i += blockDim.x) g_labels[i] = (int)l8[i];
    } else {
        for (int i = threadIdx.x; i < B; i += blockDim.x) g_labels[i] = li[i];
    }
}

// fused pack (hi/lo split) + row norms + accumulator init; reads E exactly once.
// one warp per row, lane covers 8 consecutive elements.
__global__ void prep_kernel(const float* __restrict__ E) {
    int warp = threadIdx.x >> 5, lane = threadIdx.x & 31;
    int row = blockIdx.x * 8 + warp;
    if (threadIdx.x < 8) {
        int idx = blockIdx.x * 8 + threadIdx.x;
        g_vpos[idx] = 0u;
        g_vneg[idx] = 0xFFFFFFFFu;
    }
    const float4* e4 = (const float4*)(E + (size_t)row * Ddim);
    float4 v[2];
    v[0] = e4[lane * 2];
    v[1] = e4[lane * 2 + 1];
    float x[8] = {v[0].x, v[0].y, v[0].z, v[0].w, v[1].x, v[1].y, v[1].z, v[1].w};
    float s = 0.f;
    __nv_bfloat16 h[8], l[8];
    #pragma unroll
    for (int i = 0; i < 8; i++) {
        s += x[i] * x[i];
        h[i] = __float2bfloat16(x[i]);
        l[i] = __float2bfloat16(x[i] - __bfloat162float(h[i]));
    }
    size_t off = (size_t)row * Ddim + lane * 8;
    *(uint4*)(g_hi + off) = *(const uint4*)h;
    *(uint4*)(g_lo + off) = *(const uint4*)l;
    #pragma unroll
    for (int o = 16; o; o >>= 1) s += __shfl_xor_sync(0xFFFFFFFFu, s, o);
    if (lane == 0) {
        g_norms[row] = s;
        g_njl[row] = make_float2(s, __int_as_float(g_labels[row]));
    }
}

// ---------------- main fused kernel ----------------
__global__ __launch_bounds__(512, 1) void mine_kernel() {
    extern __shared__ char smem[];
    const uint32_t sb = smem_u32(smem);
    const int tid  = threadIdx.x;
    const int wid  = tid >> 5;
    const int lane = tid & 31;
    const int wr   = wid & 3;
    const int wc   = wid >> 2;

    int it = 0, rem = blockIdx.x;
    while (rem >= NT - it) { rem -= NT - it; it++; }
    const int jt   = it + rem;
    const int row0 = it * 128;
    const int col0 = jt * 128;

    if (tid < 128)      ((float2*)(smem + SM_NJR))[tid]       = g_njl[row0 + tid];
    else if (tid < 256) ((float2*)(smem + SM_NJC))[tid - 128] = g_njl[col0 + tid - 128];

    auto issue_chunk = [&](int kc, int b) {
        #pragma unroll
        for (int i = 0; i < 8; i++) {
            int u   = i * 512 + tid;
            int arr = u >> 10;
            int s   = u & 1023;
            int r   = s >> 3;
            int q   = s & 7;
            const __nv_bfloat16* base = (arr & 1) ? g_lo : g_hi;
            int grow = ((arr >> 1) ? col0 : row0) + r;
            const void* src = base + (size_t)grow * Ddim + kc * 64 + q * 8;
            uint32_t dst = sb + SM_ARR(b, arr) + swz((uint32_t)(r * 128 + q * 16));
            cp_async16(dst, src);
        }
        cp_commit();
    };

    float acc[2][4][4];
    #pragma unroll
    for (int ar = 0; ar < 2; ar++)
        #pragma unroll
        for (int ac = 0; ac < 4; ac++)
            #pragma unroll
            for (int e = 0; e < 4; e++) acc[ar][ac][e] = 0.f;

    const int Rb = wr * 32;
    const int Cb = wc * 32;
    const int seg = lane >> 3;
    const int l7  = lane & 7;
    const int a_radd = (seg & 1) * 8 + l7;
    const int a_koff = (seg >> 1) * 16;
    const int b_radd = (seg >> 1) * 8 + l7;
    const int b_koff = (seg & 1) * 16;

    issue_chunk(0, 0);
    #pragma unroll
    for (int kc = 0; kc < 4; kc++) {
        const int b = kc & 1;
        if (kc < 3) { issue_chunk(kc + 1, b ^ 1); cp_wait<1>(); }
        else        { cp_wait<0>(); }
        __syncthreads();

        #pragma unroll
        for (int ks = 0; ks < 4; ks++) {
            uint32_t ah[2][4], al[2][4], bh[2][4], bl[2][4];
            #pragma unroll
            for (int ar = 0; ar < 2; ar++) {
                uint32_t off = swz((uint32_t)((Rb + ar * 16 + a_radd) * 128 + ks * 32 + a_koff));
                ldm_x4(ah[ar], sb + SM_ARR(b, 0) + off);
                ldm_x4(al[ar], sb + SM_ARR(b, 1) + off);
            }
            #pragma unroll
            for (int cp = 0; cp < 2; cp++) {
                uint32_t off = swz((uint32_t)((Cb + cp * 16 + b_radd) * 128 + ks * 32 + b_koff));
                ldm_x4(bh[cp], sb + SM_ARR(b, 2) + off);
                ldm_x4(bl[cp], sb + SM_ARR(b, 3) + off);
            }
            // pass-major ordering: 8 independent accumulators per pass, so
            // accumulator reuse distance = 8 MMAs (~64cyc) > HMMA latency.
            #pragma unroll
            for (int ar = 0; ar < 2; ar++)
                #pragma unroll
                for (int ac = 0; ac < 4; ac++) {
                    const int cp = ac >> 1, sel = (ac & 1) * 2;
                    mma16816(acc[ar][ac], ah[ar], bh[cp][sel], bh[cp][sel + 1]);
                }
            #pragma unroll
            for (int ar = 0; ar < 2; ar++)
                #pragma unroll
                for (int ac = 0; ac < 4; ac++) {
                    const int cp = ac >> 1, sel = (ac & 1) * 2;
                    mma16816(acc[ar][ac], ah[ar], bl[cp][sel], bl[cp][sel + 1]);
                }
            #pragma unroll
            for (int ar = 0; ar < 2; ar++)
                #pragma unroll
                for (int ac = 0; ac < 4; ac++) {
                    const int cp = ac >> 1, sel = (ac & 1) * 2;
                    mma16816(acc[ar][ac], al[ar], bh[cp][sel], bh[cp][sel + 1]);
                }
        }
        __syncthreads();
    }

    // ---- epilogue: dual-direction batch-hard fold ----
    const int g  = lane >> 2;
    const int qp = lane & 3;

    int   rowG[4]; float nR[4]; int lR[4];
    int   colG[8]; float nC[8]; int lC[8];
    const float2* njr = (const float2*)(smem + SM_NJR);
    const float2* njc = (const float2*)(smem + SM_NJC);
    #pragma unroll
    for (int ar = 0; ar < 2; ar++)
        #pragma unroll
        for (int h = 0; h < 2; h++) {
            int lr = Rb + ar * 16 + g + h * 8;
            int k = ar * 2 + h;
            rowG[k] = row0 + lr;
            nR[k] = njr[lr].x; lR[k] = __float_as_int(njr[lr].y);
        }
    #pragma unroll
    for (int ac = 0; ac < 4; ac++)
        #pragma unroll
        for (int p = 0; p < 2; p++) {
            int lc = Cb + ac * 8 + qp * 2 + p;
            int k = ac * 2 + p;
            colG[k] = col0 + lc;
            nC[k] = njc[lc].x; lC[k] = __float_as_int(njc[lc].y);
        }

    float rp[4], rn[4], cpx[8], cn[8];
    #pragma unroll
    for (int k = 0; k < 4; k++) { rp[k] = -1e30f; rn[k] = 1e30f; }
    #pragma unroll
    for (int k = 0; k < 8; k++) { cpx[k] = -1e30f; cn[k] = 1e30f; }

    #pragma unroll
    for (int ar = 0; ar < 2; ar++)
        #pragma unroll
        for (int ac = 0; ac < 4; ac++)
            #pragma unroll
            for (int e = 0; e < 4; e++) {
                const int ri = ar * 2 + (e >> 1);
                const int ci = ac * 2 + (e & 1);
                const float w  = -2.f * acc[ar][ac][e];
                const float vr = w + nC[ci];
                const float vc = w + nR[ri];
                if (lR[ri] == lC[ci]) {
                    if (rowG[ri] != colG[ci]) {
                        rp[ri]  = fmaxf(rp[ri], vr);
                        cpx[ci] = fmaxf(cpx[ci], vc);
                    }
                } else {
                    rn[ri] = fminf(rn[ri], vr);
                    cn[ci] = fminf(cn[ci], vc);
                }
            }

    #pragma unroll
    for (int o = 1; o <= 2; o <<= 1)
        #pragma unroll
        for (int k = 0; k < 4; k++) {
            rp[k] = fmaxf(rp[k], __shfl_xor_sync(0xFFFFFFFFu, rp[k], o));
            rn[k] = fminf(rn[k], __shfl_xor_sync(0xFFFFFFFFu, rn[k], o));
        }
    #pragma unroll
    for (int o = 4; o <= 16; o <<= 1)
        #pragma unroll
        for (int k = 0; k < 8; k++) {
            cpx[k] = fmaxf(cpx[k], __shfl_xor_sync(0xFFFFFFFFu, cpx[k], o));
            cn[k]  = fminf(cn[k],  __shfl_xor_sync(0xFFFFFFFFu, cn[k], o));
        }

    if (qp == 0) {
        #pragma unroll
        for (int k = 0; k < 4; k++) {
            if (rp[k] > -1e29f) atomicMax(&g_vpos[rowG[k]], enc(rp[k]));
            if (rn[k] <  1e29f) atomicMin(&g_vneg[rowG[k]], enc(rn[k]));
        }
    }
    if (g == 0) {
        #pragma unroll
        for (int k = 0; k < 8; k++) {
            if (cpx[k] > -1e29f) atomicMax(&g_vpos[colG[k]], enc(cpx[k]));
            if (cn[k]  <  1e29f) atomicMin(&g_vneg[colG[k]], enc(cn[k]));
        }
    }
}

// ---------------- finalize ----------------
__global__ void finalize_kernel(float* out) {
    __shared__ float ss[32], sv[32];
    int tid = threadIdx.x;
    float s = 0.f, v = 0.f;
    for (int i = tid; i < Bsz; i += blockDim.x) {
        float vp = dec(g_vpos[i]);
        float vn = dec(g_vneg[i]);
        if (vp > -1e29f && vn < 1e29f) {
            float ni = g_norms[i];
            float dp = sqrtf(fmaxf(vp + ni, 0.f));
            float dn = sqrtf(fmaxf(vn + ni, 0.f));
            s += fmaxf(dp - dn + MARGIN, 0.f);
            v += 1.f;
        }
    }
    #pragma unroll
    for (int o = 16; o; o >>= 1) {
        s += __shfl_xor_sync(0xFFFFFFFFu, s, o);
        v += __shfl_xor_sync(0xFFFFFFFFu, v, o);
    }
    int warp = tid >> 5, lane = tid & 31;
    if (lane == 0) { ss[warp] = s; sv[warp] = v; }
    __syncthreads();
    if (warp == 0) {
        int nw = blockDim.x >> 5;
        s = (lane < nw) ? ss[lane] : 0.f;
        v = (lane < nw) ? sv[lane] : 0.f;
        #pragma unroll
        for (int o = 16; o; o >>= 1) {
            s += __shfl_xor_sync(0xFFFFFFFFu, s, o);
            v += __shfl_xor_sync(0xFFFFFFFFu, v, o);
        }
        if (lane == 0) out[0] = (v > 0.f) ? (s / fmaxf(v, 1.f)) : 0.f;
    }
}

extern "C" void kernel_launch(void* const* d_in, const int* in_sizes, int n_in,
                              void* d_out, int out_size) {
    const float* E   = (const float*)d_in[0];
    const void*  lab = d_in[1];
    int B = in_sizes[1];

    cudaFuncSetAttribute(mine_kernel, cudaFuncAttributeMaxDynamicSharedMemorySize, SMEM_TOTAL);

    labels_kernel<<<1, 256>>>(lab, B);
    prep_kernel<<<Bsz / 8, 256>>>(E);
    mine_kernel<<<NTILES, 512, SMEM_TOTAL>>>();
    finalize_kernel<<<1, 1024>>>((float*)d_out);
}

// round 6
// speedup vs baseline: 9.8125x; 1.2256x over previous
#include <cuda_runtime.h>
#include <cuda_bf16.h>
#include <math.h>
#include <stdint.h>

#define Bsz    8192
#define Ddim   256
#define MARGIN 0.3f
#define NT     64
#define NTILES (NT * (NT + 1) / 2)   // 2080

// ---- dynamic SMEM layout ----
// 2 k-chunk buffers x 3 arrays (Ah, Bh, Bl) x [128 rows][128 bytes] = 98304
#define SM_BUF(b)      ((b) * 49152)
#define SM_ARR(b, a)   (SM_BUF(b) + (a) * 16384)
#define SM_NJR         98304
#define SM_NJC         99328
#define SMEM_TOTAL     100352

// ---- device globals ----
__device__ float         g_norms[Bsz];
__device__ int           g_labels[Bsz];
__device__ float2        g_njl[Bsz];
__device__ __nv_bfloat16 g_hi[Bsz * Ddim];
__device__ __nv_bfloat16 g_lo[Bsz * Ddim];
__device__ uint2         g_v[Bsz];       // {enc(max pos v), enc(min neg v)}

__device__ __forceinline__ unsigned int enc(float f) {
    unsigned int u = __float_as_uint(f);
    return (u & 0x80000000u) ? ~u : (u | 0x80000000u);
}
__device__ __forceinline__ float dec(unsigned int u) {
    return (u & 0x80000000u) ? __uint_as_float(u ^ 0x80000000u) : __uint_as_float(~u);
}
__device__ __forceinline__ uint32_t smem_u32(const void* p) {
    uint32_t a;
    asm("{ .reg .u64 t; cvta.to.shared.u64 t, %1; cvt.u32.u64 %0, t; }" : "=r"(a) : "l"(p));
    return a;
}
__device__ __forceinline__ void cp_async16(uint32_t dst, const void* src) {
    asm volatile("cp.async.cg.shared.global [%0], [%1], 16;" :: "r"(dst), "l"(src) : "memory");
}
__device__ __forceinline__ void cp_commit() {
    asm volatile("cp.async.commit_group;" ::: "memory");
}
template <int N>
__device__ __forceinline__ void cp_wait() {
    asm volatile("cp.async.wait_group %0;" :: "n"(N) : "memory");
}
__device__ __forceinline__ void ldm_x4(uint32_t r[4], uint32_t addr) {
    asm volatile("ldmatrix.sync.aligned.m8n8.x4.shared.b16 {%0,%1,%2,%3}, [%4];"
                 : "=r"(r[0]), "=r"(r[1]), "=r"(r[2]), "=r"(r[3]) : "r"(addr));
}
__device__ __forceinline__ void mma16816(float d[4], const uint32_t a[4],
                                         uint32_t b0, uint32_t b1) {
    asm volatile(
        "mma.sync.aligned.m16n8k16.row.col.f32.bf16.bf16.f32 "
        "{%0,%1,%2,%3},{%4,%5,%6,%7},{%8,%9},{%0,%1,%2,%3};"
        : "+f"(d[0]), "+f"(d[1]), "+f"(d[2]), "+f"(d[3])
        : "r"(a[0]), "r"(a[1]), "r"(a[2]), "r"(a[3]), "r"(b0), "r"(b1));
}
__device__ __forceinline__ uint32_t swz(uint32_t off) {
    return off ^ ((off >> 3) & 0x70);
}

// ---------------- prep ----------------
__global__ void labels_kernel(const void* lab, int B) {
    __shared__ int is64;
    const int* li = (const int*)lab;
    if (threadIdx.x == 0) {
        int all0 = 1;
        #pragma unroll
        for (int i = 0; i < 32; i++)
            if (li[2 * i + 1] != 0) all0 = 0;
        is64 = all0;
    }
    __syncthreads();
    if (is64) {
        const long long* l8 = (const long long*)lab;
        for (int i = threadIdx.x; i < B; i += blockDim.x) g_labels[i] = (int)l8[i];
    } else {
        for (int i = threadIdx.x; i < B; i += blockDim.x) g_labels[i] = li[i];
    }
}

// fused pack (hi/lo split) + row norms + accumulator init; reads E exactly once.
__global__ void prep_kernel(const float* __restrict__ E) {
    int warp = threadIdx.x >> 5, lane = threadIdx.x & 31;
    int row = blockIdx.x * 8 + warp;
    if (threadIdx.x < 8) {
        int idx = blockIdx.x * 8 + threadIdx.x;
        g_v[idx] = make_uint2(0u, 0xFFFFFFFFu);
    }
    const float4* e4 = (const float4*)(E + (size_t)row * Ddim);
    float4 v[2];
    v[0] = e4[lane * 2];
    v[1] = e4[lane * 2 + 1];
    float x[8] = {v[0].x, v[0].y, v[0].z, v[0].w, v[1].x, v[1].y, v[1].z, v[1].w};
    float s = 0.f;
    __nv_bfloat16 h[8], l[8];
    #pragma unroll
    for (int i = 0; i < 8; i++) {
        s += x[i] * x[i];
        h[i] = __float2bfloat16(x[i]);
        l[i] = __float2bfloat16(x[i] - __bfloat162float(h[i]));
    }
    size_t off = (size_t)row * Ddim + lane * 8;
    *(uint4*)(g_hi + off) = *(const uint4*)h;
    *(uint4*)(g_lo + off) = *(const uint4*)l;
    #pragma unroll
    for (int o = 16; o; o >>= 1) s += __shfl_xor_sync(0xFFFFFFFFu, s, o);
    if (lane == 0) {
        g_norms[row] = s;
        g_njl[row] = make_float2(s, __int_as_float(g_labels[row]));
    }
}

// ---------------- main fused kernel ----------------
// 2-pass precision: dot ~= ah*bh + ah*bl  (al*bh dropped; error ~1e-5 on loss)
__global__ __launch_bounds__(512, 1) void mine_kernel() {
    extern __shared__ char smem[];
    const uint32_t sb = smem_u32(smem);
    const int tid  = threadIdx.x;
    const int wid  = tid >> 5;
    const int lane = tid & 31;
    const int wr   = wid & 3;
    const int wc   = wid >> 2;

    int it = 0, rem = blockIdx.x;
    while (rem >= NT - it) { rem -= NT - it; it++; }
    const int jt   = it + rem;
    const int row0 = it * 128;
    const int col0 = jt * 128;

    if (tid < 128)      ((float2*)(smem + SM_NJR))[tid]       = g_njl[row0 + tid];
    else if (tid < 256) ((float2*)(smem + SM_NJC))[tid - 128] = g_njl[col0 + tid - 128];

    // 3 arrays x 1024 16B segs = 3072; 6 per thread
    auto issue_chunk = [&](int kc, int b) {
        #pragma unroll
        for (int i = 0; i < 6; i++) {
            int u   = i * 512 + tid;
            int arr = u >> 10;              // 0=A-hi, 1=B-hi, 2=B-lo
            int s   = u & 1023;
            int r   = s >> 3;
            int q   = s & 7;
            const __nv_bfloat16* base = (arr == 2) ? g_lo : g_hi;
            int grow = (arr ? col0 : row0) + r;
            const void* src = base + (size_t)grow * Ddim + kc * 64 + q * 8;
            uint32_t dst = sb + SM_ARR(b, arr) + swz((uint32_t)(r * 128 + q * 16));
            cp_async16(dst, src);
        }
        cp_commit();
    };

    float acc[2][4][4];
    #pragma unroll
    for (int ar = 0; ar < 2; ar++)
        #pragma unroll
        for (int ac = 0; ac < 4; ac++)
            #pragma unroll
            for (int e = 0; e < 4; e++) acc[ar][ac][e] = 0.f;

    const int Rb = wr * 32;
    const int Cb = wc * 32;
    const int seg = lane >> 3;
    const int l7  = lane & 7;
    const int a_radd = (seg & 1) * 8 + l7;
    const int a_koff = (seg >> 1) * 16;
    const int b_radd = (seg >> 1) * 8 + l7;
    const int b_koff = (seg & 1) * 16;

    issue_chunk(0, 0);
    #pragma unroll
    for (int kc = 0; kc < 4; kc++) {
        const int b = kc & 1;
        if (kc < 3) { issue_chunk(kc + 1, b ^ 1); cp_wait<1>(); }
        else        { cp_wait<0>(); }
        __syncthreads();

        #pragma unroll
        for (int ks = 0; ks < 4; ks++) {
            uint32_t ah[2][4], bh[2][4], bl[2][4];
            #pragma unroll
            for (int ar = 0; ar < 2; ar++) {
                uint32_t off = swz((uint32_t)((Rb + ar * 16 + a_radd) * 128 + ks * 32 + a_koff));
                ldm_x4(ah[ar], sb + SM_ARR(b, 0) + off);
            }
            #pragma unroll
            for (int cp = 0; cp < 2; cp++) {
                uint32_t off = swz((uint32_t)((Cb + cp * 16 + b_radd) * 128 + ks * 32 + b_koff));
                ldm_x4(bh[cp], sb + SM_ARR(b, 1) + off);
                ldm_x4(bl[cp], sb + SM_ARR(b, 2) + off);
            }
            #pragma unroll
            for (int ar = 0; ar < 2; ar++)
                #pragma unroll
                for (int ac = 0; ac < 4; ac++) {
                    const int cp = ac >> 1, sel = (ac & 1) * 2;
                    mma16816(acc[ar][ac], ah[ar], bh[cp][sel], bh[cp][sel + 1]);
                }
            #pragma unroll
            for (int ar = 0; ar < 2; ar++)
                #pragma unroll
                for (int ac = 0; ac < 4; ac++) {
                    const int cp = ac >> 1, sel = (ac & 1) * 2;
                    mma16816(acc[ar][ac], ah[ar], bl[cp][sel], bl[cp][sel + 1]);
                }
        }
        __syncthreads();
    }

    // ---- epilogue: dual-direction batch-hard fold ----
    const int g  = lane >> 2;
    const int qp = lane & 3;

    int   rowG[4]; float nR[4]; int lR[4];
    int   colG[8]; float nC[8]; int lC[8];
    const float2* njr = (const float2*)(smem + SM_NJR);
    const float2* njc = (const float2*)(smem + SM_NJC);
    #pragma unroll
    for (int ar = 0; ar < 2; ar++)
        #pragma unroll
        for (int h = 0; h < 2; h++) {
            int lr = Rb + ar * 16 + g + h * 8;
            int k = ar * 2 + h;
            rowG[k] = row0 + lr;
            nR[k] = njr[lr].x; lR[k] = __float_as_int(njr[lr].y);
        }
    #pragma unroll
    for (int ac = 0; ac < 4; ac++)
        #pragma unroll
        for (int p = 0; p < 2; p++) {
            int lc = Cb + ac * 8 + qp * 2 + p;
            int k = ac * 2 + p;
            colG[k] = col0 + lc;
            nC[k] = njc[lc].x; lC[k] = __float_as_int(njc[lc].y);
        }

    float rp[4], rn[4], cpx[8], cn[8];
    #pragma unroll
    for (int k = 0; k < 4; k++) { rp[k] = -1e30f; rn[k] = 1e30f; }
    #pragma unroll
    for (int k = 0; k < 8; k++) { cpx[k] = -1e30f; cn[k] = 1e30f; }

    #pragma unroll
    for (int ar = 0; ar < 2; ar++)
        #pragma unroll
        for (int ac = 0; ac < 4; ac++)
            #pragma unroll
            for (int e = 0; e < 4; e++) {
                const int ri = ar * 2 + (e >> 1);
                const int ci = ac * 2 + (e & 1);
                const float w  = -2.f * acc[ar][ac][e];
                const float vr = w + nC[ci];
                const float vc = w + nR[ri];
                if (lR[ri] == lC[ci]) {
                    if (rowG[ri] != colG[ci]) {
                        rp[ri]  = fmaxf(rp[ri], vr);
                        cpx[ci] = fmaxf(cpx[ci], vc);
                    }
                } else {
                    rn[ri] = fminf(rn[ri], vr);
                    cn[ci] = fminf(cn[ci], vc);
                }
            }

    #pragma unroll
    for (int o = 1; o <= 2; o <<= 1)
        #pragma unroll
        for (int k = 0; k < 4; k++) {
            rp[k] = fmaxf(rp[k], __shfl_xor_sync(0xFFFFFFFFu, rp[k], o));
            rn[k] = fminf(rn[k], __shfl_xor_sync(0xFFFFFFFFu, rn[k], o));
        }
    #pragma unroll
    for (int o = 4; o <= 16; o <<= 1)
        #pragma unroll
        for (int k = 0; k < 8; k++) {
            cpx[k] = fmaxf(cpx[k], __shfl_xor_sync(0xFFFFFFFFu, cpx[k], o));
            cn[k]  = fminf(cn[k],  __shfl_xor_sync(0xFFFFFFFFu, cn[k], o));
        }

    if (qp == 0) {
        #pragma unroll
        for (int k = 0; k < 4; k++) {
            if (rp[k] > -1e29f) atomicMax(&g_v[rowG[k]].x, enc(rp[k]));
            if (rn[k] <  1e29f) atomicMin(&g_v[rowG[k]].y, enc(rn[k]));
        }
    }
    if (g == 0) {
        #pragma unroll
        for (int k = 0; k < 8; k++) {
            if (cpx[k] > -1e29f) atomicMax(&g_v[colG[k]].x, enc(cpx[k]));
            if (cn[k]  <  1e29f) atomicMin(&g_v[colG[k]].y, enc(cn[k]));
        }
    }
}

// ---------------- finalize ----------------
__global__ void finalize_kernel(float* out) {
    __shared__ float ss[32], sv[32];
    int tid = threadIdx.x;
    float s = 0.f, v = 0.f;
    #pragma unroll
    for (int i = tid; i < Bsz; i += 1024) {
        uint2 u = g_v[i];
        float vp = dec(u.x);
        float vn = dec(u.y);
        if (vp > -1e29f && vn < 1e29f) {
            float ni = g_norms[i];
            float dp = sqrtf(fmaxf(vp + ni, 0.f));
            float dn = sqrtf(fmaxf(vn + ni, 0.f));
            s += fmaxf(dp - dn + MARGIN, 0.f);
            v += 1.f;
        }
    }
    #pragma unroll
    for (int o = 16; o; o >>= 1) {
        s += __shfl_xor_sync(0xFFFFFFFFu, s, o);
        v += __shfl_xor_sync(0xFFFFFFFFu, v, o);
    }
    int warp = tid >> 5, lane = tid & 31;
    if (lane == 0) { ss[warp] = s; sv[warp] = v; }
    __syncthreads();
    if (warp == 0) {
        s = (lane < 32) ? ss[lane] : 0.f;
        v = (lane < 32) ? sv[lane] : 0.f;
        #pragma unroll
        for (int o = 16; o; o >>= 1) {
            s += __shfl_xor_sync(0xFFFFFFFFu, s, o);
            v += __shfl_xor_sync(0xFFFFFFFFu, v, o);
        }
        if (lane == 0) out[0] = (v > 0.f) ? (s / fmaxf(v, 1.f)) : 0.f;
    }
}

extern "C" void kernel_launch(void* const* d_in, const int* in_sizes, int n_in,
                              void* d_out, int out_size) {
    const float* E   = (const float*)d_in[0];
    const void*  lab = d_in[1];
    int B = in_sizes[1];

    cudaFuncSetAttribute(mine_kernel, cudaFuncAttributeMaxDynamicSharedMemorySize, SMEM_TOTAL);

    labels_kernel<<<1, 256>>>(lab, B);
    prep_kernel<<<Bsz / 8, 256>>>(E);
    mine_kernel<<<NTILES, 512, SMEM_TOTAL>>>();
    finalize_kernel<<<1, 1024>>>((float*)d_out);
}

// round 7
// speedup vs baseline: 10.6069x; 1.0810x over previous
#include <cuda_runtime.h>
#include <cuda_bf16.h>
#include <math.h>
#include <stdint.h>

#define Bsz    8192
#define Ddim   256
#define MARGIN 0.3f
#define NT     64
#define NTILES (NT * (NT + 1) / 2)   // 2080

// ---- dynamic SMEM: 2 bufs x 3 arrays (Ah, Bh, Bl) x 16KB ----
#define SM_BUF(b)      ((b) * 49152)
#define SM_ARR(b, a)   (SM_BUF(b) + (a) * 16384)
#define SM_NJR         98304
#define SM_NJC         99328
#define SMEM_TOTAL     100352

__device__ float         g_norms[Bsz];
__device__ float2        g_njl[Bsz];
__device__ __nv_bfloat16 g_hi[Bsz * Ddim];
__device__ __nv_bfloat16 g_lo[Bsz * Ddim];
__device__ uint2         g_v[Bsz];       // {enc(max pos v), enc(min neg v)}

__device__ __forceinline__ unsigned int enc(float f) {
    unsigned int u = __float_as_uint(f);
    return (u & 0x80000000u) ? ~u : (u | 0x80000000u);
}
__device__ __forceinline__ float dec(unsigned int u) {
    return (u & 0x80000000u) ? __uint_as_float(u ^ 0x80000000u) : __uint_as_float(~u);
}
__device__ __forceinline__ uint32_t smem_u32(const void* p) {
    uint32_t a;
    asm("{ .reg .u64 t; cvta.to.shared.u64 t, %1; cvt.u32.u64 %0, t; }" : "=r"(a) : "l"(p));
    return a;
}
__device__ __forceinline__ void cp_async16(uint32_t dst, const void* src) {
    asm volatile("cp.async.cg.shared.global [%0], [%1], 16;" :: "r"(dst), "l"(src) : "memory");
}
__device__ __forceinline__ void cp_commit() {
    asm volatile("cp.async.commit_group;" ::: "memory");
}
template <int N>
__device__ __forceinline__ void cp_wait() {
    asm volatile("cp.async.wait_group %0;" :: "n"(N) : "memory");
}
__device__ __forceinline__ void ldm_x4(uint32_t r[4], uint32_t addr) {
    asm volatile("ldmatrix.sync.aligned.m8n8.x4.shared.b16 {%0,%1,%2,%3}, [%4];"
                 : "=r"(r[0]), "=r"(r[1]), "=r"(r[2]), "=r"(r[3]) : "r"(addr));
}
__device__ __forceinline__ void mma16816(float d[4], const uint32_t a[4],
                                         uint32_t b0, uint32_t b1) {
    asm volatile(
        "mma.sync.aligned.m16n8k16.row.col.f32.bf16.bf16.f32 "
        "{%0,%1,%2,%3},{%4,%5,%6,%7},{%8,%9},{%0,%1,%2,%3};"
        : "+f"(d[0]), "+f"(d[1]), "+f"(d[2]), "+f"(d[3])
        : "r"(a[0]), "r"(a[1]), "r"(a[2]), "r"(a[3]), "r"(b0), "r"(b1));
}
__device__ __forceinline__ uint32_t swz(uint32_t off) {
    return off ^ ((off >> 3) & 0x70);
}

// ---------------- prep: pack hi/lo + norms + njl + accumulator init ----------------
// one warp per row; label dtype (int32 vs int64) detected inline by lane 0.
__global__ void prep_kernel(const float* __restrict__ E, const void* __restrict__ lab) {
    int warp = threadIdx.x >> 5, lane = threadIdx.x & 31;
    int row = blockIdx.x * 8 + warp;
    if (threadIdx.x < 8) {
        int idx = blockIdx.x * 8 + threadIdx.x;
        g_v[idx] = make_uint2(0u, 0xFFFFFFFFu);
    }
    const float4* e4 = (const float4*)(E + (size_t)row * Ddim);
    float4 v[2];
    v[0] = e4[lane * 2];
    v[1] = e4[lane * 2 + 1];
    float x[8] = {v[0].x, v[0].y, v[0].z, v[0].w, v[1].x, v[1].y, v[1].z, v[1].w};
    float s = 0.f;
    __nv_bfloat16 h[8], l[8];
    #pragma unroll
    for (int i = 0; i < 8; i++) {
        s += x[i] * x[i];
        h[i] = __float2bfloat16(x[i]);
        l[i] = __float2bfloat16(x[i] - __bfloat162float(h[i]));
    }
    size_t off = (size_t)row * Ddim + lane * 8;
    *(uint4*)(g_hi + off) = *(const uint4*)h;
    *(uint4*)(g_lo + off) = *(const uint4*)l;
    #pragma unroll
    for (int o = 16; o; o >>= 1) s += __shfl_xor_sync(0xFFFFFFFFu, s, o);
    if (lane == 0) {
        // dtype detect: int64 labels in [0,512) have zero odd words (first 32 pairs)
        const int* li = (const int*)lab;
        int all0 = 1;
        #pragma unroll
        for (int i = 0; i < 32; i++)
            if (li[2 * i + 1] != 0) all0 = 0;
        int lb = all0 ? (int)((const long long*)lab)[row] : li[row];
        g_norms[row] = s;
        g_njl[row] = make_float2(s, __int_as_float(lb));
    }
}

// ---------------- main fused kernel ----------------
// 256 threads, 8 warps (2 row-groups x 4 col-groups); warp tile 64x32.
// 2-pass precision: dot ~= ah*bh + ah*bl.
__global__ __launch_bounds__(256, 1) void mine_kernel() {
    extern __shared__ char smem[];
    const uint32_t sb = smem_u32(smem);
    const int tid  = threadIdx.x;
    const int wid  = tid >> 5;
    const int lane = tid & 31;
    const int wr   = wid & 1;          // 64-row group
    const int wc   = wid >> 1;         // 32-col group

    int it = 0, rem = blockIdx.x;
    while (rem >= NT - it) { rem -= NT - it; it++; }
    const int jt   = it + rem;
    const int row0 = it * 128;
    const int col0 = jt * 128;

    if (tid < 128)      ((float2*)(smem + SM_NJR))[tid]       = g_njl[row0 + tid];
    else                ((float2*)(smem + SM_NJC))[tid - 128] = g_njl[col0 + tid - 128];

    // 3 arrays x 1024 16B segs = 3072; 12 per thread
    auto issue_chunk = [&](int kc, int b) {
        #pragma unroll
        for (int i = 0; i < 12; i++) {
            int u   = i * 256 + tid;
            int arr = u >> 10;              // 0=A-hi, 1=B-hi, 2=B-lo
            int s   = u & 1023;
            int r   = s >> 3;
            int q   = s & 7;
            const __nv_bfloat16* base = (arr == 2) ? g_lo : g_hi;
            int grow = (arr ? col0 : row0) + r;
            const void* src = base + (size_t)grow * Ddim + kc * 64 + q * 8;
            uint32_t dst = sb + SM_ARR(b, arr) + swz((uint32_t)(r * 128 + q * 16));
            cp_async16(dst, src);
        }
        cp_commit();
    };

    float acc[4][4][4];
    #pragma unroll
    for (int ar = 0; ar < 4; ar++)
        #pragma unroll
        for (int ac = 0; ac < 4; ac++)
            #pragma unroll
            for (int e = 0; e < 4; e++) acc[ar][ac][e] = 0.f;

    const int Rb = wr * 64;
    const int Cb = wc * 32;
    const int seg = lane >> 3;
    const int l7  = lane & 7;
    const int a_radd = (seg & 1) * 8 + l7;
    const int a_koff = (seg >> 1) * 16;
    const int b_radd = (seg >> 1) * 8 + l7;
    const int b_koff = (seg & 1) * 16;

    issue_chunk(0, 0);
    #pragma unroll
    for (int kc = 0; kc < 4; kc++) {
        const int b = kc & 1;
        if (kc < 3) { issue_chunk(kc + 1, b ^ 1); cp_wait<1>(); }
        else        { cp_wait<0>(); }
        __syncthreads();

        #pragma unroll
        for (int ks = 0; ks < 4; ks++) {
            uint32_t ah[4][4], bh[2][4], bl[2][4];
            #pragma unroll
            for (int ar = 0; ar < 4; ar++) {
                uint32_t off = swz((uint32_t)((Rb + ar * 16 + a_radd) * 128 + ks * 32 + a_koff));
                ldm_x4(ah[ar], sb + SM_ARR(b, 0) + off);
            }
            #pragma unroll
            for (int cp = 0; cp < 2; cp++) {
                uint32_t off = swz((uint32_t)((Cb + cp * 16 + b_radd) * 128 + ks * 32 + b_koff));
                ldm_x4(bh[cp], sb + SM_ARR(b, 1) + off);
                ldm_x4(bl[cp], sb + SM_ARR(b, 2) + off);
            }
            #pragma unroll
            for (int ar = 0; ar < 4; ar++)
                #pragma unroll
                for (int ac = 0; ac < 4; ac++) {
                    const int cp = ac >> 1, sel = (ac & 1) * 2;
                    mma16816(acc[ar][ac], ah[ar], bh[cp][sel], bh[cp][sel + 1]);
                }
            #pragma unroll
            for (int ar = 0; ar < 4; ar++)
                #pragma unroll
                for (int ac = 0; ac < 4; ac++) {
                    const int cp = ac >> 1, sel = (ac & 1) * 2;
                    mma16816(acc[ar][ac], ah[ar], bl[cp][sel], bl[cp][sel + 1]);
                }
        }
        __syncthreads();
    }

    // ---- epilogue: dual-direction batch-hard fold ----
    const int g  = lane >> 2;
    const int qp = lane & 3;

    int   rowG[8]; float nR[8]; int lR[8];
    int   colG[8]; float nC[8]; int lC[8];
    const float2* njr = (const float2*)(smem + SM_NJR);
    const float2* njc = (const float2*)(smem + SM_NJC);
    #pragma unroll
    for (int ar = 0; ar < 4; ar++)
        #pragma unroll
        for (int h = 0; h < 2; h++) {
            int lr = Rb + ar * 16 + g + h * 8;
            int k = ar * 2 + h;
            rowG[k] = row0 + lr;
            nR[k] = njr[lr].x; lR[k] = __float_as_int(njr[lr].y);
        }
    #pragma unroll
    for (int ac = 0; ac < 4; ac++)
        #pragma unroll
        for (int p = 0; p < 2; p++) {
            int lc = Cb + ac * 8 + qp * 2 + p;
            int k = ac * 2 + p;
            colG[k] = col0 + lc;
            nC[k] = njc[lc].x; lC[k] = __float_as_int(njc[lc].y);
        }

    float rp[8], rn[8], cpx[8], cn[8];
    #pragma unroll
    for (int k = 0; k < 8; k++) {
        rp[k] = -1e30f; rn[k] = 1e30f;
        cpx[k] = -1e30f; cn[k] = 1e30f;
    }

    #pragma unroll
    for (int ar = 0; ar < 4; ar++)
        #pragma unroll
        for (int ac = 0; ac < 4; ac++)
            #pragma unroll
            for (int e = 0; e < 4; e++) {
                const int ri = ar * 2 + (e >> 1);
                const int ci = ac * 2 + (e & 1);
                const float w  = -2.f * acc[ar][ac][e];
                const float vr = w + nC[ci];
                const float vc = w + nR[ri];
                if (lR[ri] == lC[ci]) {
                    if (rowG[ri] != colG[ci]) {
                        rp[ri]  = fmaxf(rp[ri], vr);
                        cpx[ci] = fmaxf(cpx[ci], vc);
                    }
                } else {
                    rn[ri] = fminf(rn[ri], vr);
                    cn[ci] = fminf(cn[ci], vc);
                }
            }

    #pragma unroll
    for (int o = 1; o <= 2; o <<= 1)
        #pragma unroll
        for (int k = 0; k < 8; k++) {
            rp[k] = fmaxf(rp[k], __shfl_xor_sync(0xFFFFFFFFu, rp[k], o));
            rn[k] = fminf(rn[k], __shfl_xor_sync(0xFFFFFFFFu, rn[k], o));
        }
    #pragma unroll
    for (int o = 4; o <= 16; o <<= 1)
        #pragma unroll
        for (int k = 0; k < 8; k++) {
            cpx[k] = fmaxf(cpx[k], __shfl_xor_sync(0xFFFFFFFFu, cpx[k], o));
            cn[k]  = fminf(cn[k],  __shfl_xor_sync(0xFFFFFFFFu, cn[k], o));
        }

    if (qp == 0) {
        #pragma unroll
        for (int k = 0; k < 8; k++) {
            if (rp[k] > -1e29f) atomicMax(&g_v[rowG[k]].x, enc(rp[k]));
            if (rn[k] <  1e29f) atomicMin(&g_v[rowG[k]].y, enc(rn[k]));
        }
    }
    if (g == 0) {
        #pragma unroll
        for (int k = 0; k < 8; k++) {
            if (cpx[k] > -1e29f) atomicMax(&g_v[colG[k]].x, enc(cpx[k]));
            if (cn[k]  <  1e29f) atomicMin(&g_v[colG[k]].y, enc(cn[k]));
        }
    }
}

// ---------------- finalize ----------------
__global__ void finalize_kernel(float* out) {
    __shared__ float ss[32], sv[32];
    int tid = threadIdx.x;
    // batched loads for MLP
    uint2 u[8]; float ni[8];
    #pragma unroll
    for (int k = 0; k < 8; k++) {
        u[k]  = g_v[tid + k * 1024];
        ni[k] = g_norms[tid + k * 1024];
    }
    float s = 0.f, v = 0.f;
    #pragma unroll
    for (int k = 0; k < 8; k++) {
        float vp = dec(u[k].x);
        float vn = dec(u[k].y);
        if (vp > -1e29f && vn < 1e29f) {
            float dp = sqrtf(fmaxf(vp + ni[k], 0.f));
            float dn = sqrtf(fmaxf(vn + ni[k], 0.f));
            s += fmaxf(dp - dn + MARGIN, 0.f);
            v += 1.f;
        }
    }
    #pragma unroll
    for (int o = 16; o; o >>= 1) {
        s += __shfl_xor_sync(0xFFFFFFFFu, s, o);
        v += __shfl_xor_sync(0xFFFFFFFFu, v, o);
    }
    int warp = tid >> 5, lane = tid & 31;
    if (lane == 0) { ss[warp] = s; sv[warp] = v; }
    __syncthreads();
    if (warp == 0) {
        s = ss[lane]; v = sv[lane];
        #pragma unroll
        for (int o = 16; o; o >>= 1) {
            s += __shfl_xor_sync(0xFFFFFFFFu, s, o);
            v += __shfl_xor_sync(0xFFFFFFFFu, v, o);
        }
        if (lane == 0) out[0] = (v > 0.f) ? (s / fmaxf(v, 1.f)) : 0.f;
    }
}

extern "C" void kernel_launch(void* const* d_in, const int* in_sizes, int n_in,
                              void* d_out, int out_size) {
    const float* E   = (const float*)d_in[0];
    const void*  lab = d_in[1];

    cudaFuncSetAttribute(mine_kernel, cudaFuncAttributeMaxDynamicSharedMemorySize, SMEM_TOTAL);

    prep_kernel<<<Bsz / 8, 256>>>(E, lab);
    mine_kernel<<<NTILES, 256, SMEM_TOTAL>>>();
    finalize_kernel<<<1, 1024>>>((float*)d_out);
}

// round 10
// speedup vs baseline: 11.5765x; 1.0914x over previous
#include <cuda_runtime.h>
#include <cuda_bf16.h>
#include <math.h>
#include <stdint.h>

#define Bsz    8192
#define Ddim   256
#define MARGIN 0.3f
#define NTC    32                 // 256-wide col tiles
#define NGRID  1056               // sum_{jt<32} (2*jt+2)

// ---- dynamic SMEM: 2 bufs x (A-hi 16KB + B-hi 32KB + B-lo 32KB) ----
#define SM_BUF(b)   ((b) * 81920)
#define SM_A        0
#define SM_BH       16384
#define SM_BL       49152
#define SM_NJR      163840
#define SM_NJC      164864
#define SMEM_TOTAL  166912

__device__ float         g_norms[Bsz];
__device__ float2        g_njl[Bsz];
__device__ __nv_bfloat16 g_hi[Bsz * Ddim];
__device__ __nv_bfloat16 g_lo[Bsz * Ddim];
__device__ uint2         g_v[Bsz];       // {enc(max pos v), enc(min neg v)}

__device__ __forceinline__ unsigned int enc(float f) {
    unsigned int u = __float_as_uint(f);
    return (u & 0x80000000u) ? ~u : (u | 0x80000000u);
}
__device__ __forceinline__ float dec(unsigned int u) {
    return (u & 0x80000000u) ? __uint_as_float(u ^ 0x80000000u) : __uint_as_float(~u);
}
__device__ __forceinline__ uint32_t smem_u32(const void* p) {
    uint32_t a;
    asm("{ .reg .u64 t; cvta.to.shared.u64 t, %1; cvt.u32.u64 %0, t; }" : "=r"(a) : "l"(p));
    return a;
}
__device__ __forceinline__ void cp_async16(uint32_t dst, const void* src) {
    asm volatile("cp.async.cg.shared.global [%0], [%1], 16;" :: "r"(dst), "l"(src) : "memory");
}
__device__ __forceinline__ void cp_commit() {
    asm volatile("cp.async.commit_group;" ::: "memory");
}
template <int N>
__device__ __forceinline__ void cp_wait() {
    asm volatile("cp.async.wait_group %0;" :: "n"(N) : "memory");
}
__device__ __forceinline__ void ldm_x4(uint32_t r[4], uint32_t addr) {
    asm volatile("ldmatrix.sync.aligned.m8n8.x4.shared.b16 {%0,%1,%2,%3}, [%4];"
                 : "=r"(r[0]), "=r"(r[1]), "=r"(r[2]), "=r"(r[3]) : "r"(addr));
}
__device__ __forceinline__ void mma16816(float d[4], const uint32_t a[4],
                                         uint32_t b0, uint32_t b1) {
    asm volatile(
        "mma.sync.aligned.m16n8k16.row.col.f32.bf16.bf16.f32 "
        "{%0,%1,%2,%3},{%4,%5,%6,%7},{%8,%9},{%0,%1,%2,%3};"
        : "+f"(d[0]), "+f"(d[1]), "+f"(d[2]), "+f"(d[3])
        : "r"(a[0]), "r"(a[1]), "r"(a[2]), "r"(a[3]), "r"(b0), "r"(b1));
}
__device__ __forceinline__ uint32_t swz(uint32_t off) {
    return off ^ ((off >> 3) & 0x70);
}

// ---------------- prep: pack hi/lo + norms + njl + accumulator init ----------------
__global__ void prep_kernel(const float* __restrict__ E, const void* __restrict__ lab) {
    int warp = threadIdx.x >> 5, lane = threadIdx.x & 31;
    int row = blockIdx.x * 8 + warp;
    if (threadIdx.x < 8) {
        int idx = blockIdx.x * 8 + threadIdx.x;
        g_v[idx] = make_uint2(0u, 0xFFFFFFFFu);
    }
    const float4* e4 = (const float4*)(E + (size_t)row * Ddim);
    float4 v[2];
    v[0] = e4[lane * 2];
    v[1] = e4[lane * 2 + 1];
    float x[8] = {v[0].x, v[0].y, v[0].z, v[0].w, v[1].x, v[1].y, v[1].z, v[1].w};
    float s = 0.f;
    __nv_bfloat16 h[8], l[8];
    #pragma unroll
    for (int i = 0; i < 8; i++) {
        s += x[i] * x[i];
        h[i] = __float2bfloat16(x[i]);
        l[i] = __float2bfloat16(x[i] - __bfloat162float(h[i]));
    }
    size_t off = (size_t)row * Ddim + lane * 8;
    *(uint4*)(g_hi + off) = *(const uint4*)h;
    *(uint4*)(g_lo + off) = *(const uint4*)l;
    #pragma unroll
    for (int o = 16; o; o >>= 1) s += __shfl_xor_sync(0xFFFFFFFFu, s, o);
    if (lane == 0) {
        const int* li = (const int*)lab;
        int all0 = 1;
        #pragma unroll
        for (int i = 0; i < 32; i++)
            if (li[2 * i + 1] != 0) all0 = 0;
        int lb = all0 ? (int)((const long long*)lab)[row] : li[row];
        g_norms[row] = s;
        g_njl[row] = make_float2(s, __int_as_float(lb));
    }
}

// ---------------- main fused kernel ----------------
// CTA tile 128 rows x 256 cols; 8 warps, each 64x64 (2 wr x 4 wc).
// 2-pass precision: dot ~= ah*bh + ah*bl.
__global__ __launch_bounds__(256, 1) void mine_kernel() {
    extern __shared__ char smem[];
    const uint32_t sb = smem_u32(smem);
    const int tid  = threadIdx.x;
    const int wid  = tid >> 5;
    const int lane = tid & 31;
    const int wr   = wid & 1;          // 64-row group
    const int wc   = wid >> 1;         // 64-col group (0..3)

    // map blockIdx -> (jt, it) with it <= 2*jt+1
    int jt = 0, rem = blockIdx.x;
    while (rem >= 2 * jt + 2) { rem -= 2 * jt + 2; jt++; }
    const int it   = rem;
    const int row0 = it * 128;
    const int col0 = jt * 256;

    if (tid < 128) ((float2*)(smem + SM_NJR))[tid] = g_njl[row0 + tid];
    ((float2*)(smem + SM_NJC))[tid] = g_njl[col0 + tid];

    // one 64-wide k-chunk = A-hi(128rx8seg) + B-hi(256rx8seg) + B-lo(256rx8seg)
    // = 5120 16B segs; 20 per thread
    auto issue_chunk = [&](int kc, int b) {
        #pragma unroll
        for (int i = 0; i < 20; i++) {
            int u = i * 256 + tid;
            const __nv_bfloat16* base;
            int s, grow;
            uint32_t arroff;
            if (u < 1024)      { s = u;        base = g_hi; grow = row0 + (s >> 3); arroff = SM_A; }
            else if (u < 3072) { s = u - 1024; base = g_hi; grow = col0 + (s >> 3); arroff = SM_BH; }
            else               { s = u - 3072; base = g_lo; grow = col0 + (s >> 3); arroff = SM_BL; }
            int r = s >> 3, q = s & 7;
            const void* src = base + (size_t)grow * Ddim + kc * 64 + q * 8;
            uint32_t dst = sb + SM_BUF(b) + arroff + swz((uint32_t)(r * 128 + q * 16));
            cp_async16(dst, src);
        }
        cp_commit();
    };

    float acc[4][8][4];
    #pragma unroll
    for (int ar = 0; ar < 4; ar++)
        #pragma unroll
        for (int na = 0; na < 8; na++)
            #pragma unroll
            for (int e = 0; e < 4; e++) acc[ar][na][e] = 0.f;

    const int Rb = wr * 64;
    const int Cb = wc * 64;
    const int seg = lane >> 3;
    const int l7  = lane & 7;
    const int a_radd = (seg & 1) * 8 + l7;
    const int a_koff = (seg >> 1) * 16;
    const int b_radd = (seg >> 1) * 8 + l7;
    const int b_koff = (seg & 1) * 16;

    issue_chunk(0, 0);
    #pragma unroll
    for (int kc = 0; kc < 4; kc++) {
        const int b = kc & 1;
        if (kc < 3) { issue_chunk(kc + 1, b ^ 1); cp_wait<1>(); }
        else        { cp_wait<0>(); }
        __syncthreads();

        #pragma unroll
        for (int ks = 0; ks < 4; ks++) {
            uint32_t ah[4][4], bh[4][4], bl[4][4];
            #pragma unroll
            for (int ar = 0; ar < 4; ar++) {
                uint32_t off = swz((uint32_t)((Rb + ar * 16 + a_radd) * 128 + ks * 32 + a_koff));
                ldm_x4(ah[ar], sb + SM_BUF(b) + SM_A + off);
            }
            #pragma unroll
            for (int i = 0; i < 4; i++) {
                uint32_t off = swz((uint32_t)((Cb + i * 16 + b_radd) * 128 + ks * 32 + b_koff));
                ldm_x4(bh[i], sb + SM_BUF(b) + SM_BH + off);
                ldm_x4(bl[i], sb + SM_BUF(b) + SM_BL + off);
            }
            #pragma unroll
            for (int ar = 0; ar < 4; ar++)
                #pragma unroll
                for (int na = 0; na < 8; na++) {
                    const int i = na >> 1, sel = (na & 1) * 2;
                    mma16816(acc[ar][na], ah[ar], bh[i][sel], bh[i][sel + 1]);
                }
            #pragma unroll
            for (int ar = 0; ar < 4; ar++)
                #pragma unroll
                for (int na = 0; na < 8; na++) {
                    const int i = na >> 1, sel = (na & 1) * 2;
                    mma16816(acc[ar][na], ah[ar], bl[i][sel], bl[i][sel + 1]);
                }
        }
        __syncthreads();
    }

    // ---- epilogue: dual-direction batch-hard fold ----
    const int g  = lane >> 2;
    const int qp = lane & 3;

    int   rowG[8];  float nR[8];  int lR[8];
    int   colG[16]; float nC[16]; int lC[16];
    const float2* njr = (const float2*)(smem + SM_NJR);
    const float2* njc = (const float2*)(smem + SM_NJC);
    #pragma unroll
    for (int ar = 0; ar < 4; ar++)
        #pragma unroll
        for (int h = 0; h < 2; h++) {
            int lr = Rb + ar * 16 + g + h * 8;
            int k = ar * 2 + h;
            rowG[k] = row0 + lr;
            nR[k] = njr[lr].x; lR[k] = __float_as_int(njr[lr].y);
        }
    #pragma unroll
    for (int na = 0; na < 8; na++)
        #pragma unroll
        for (int p = 0; p < 2; p++) {
            int lc = Cb + na * 8 + qp * 2 + p;
            int k = na * 2 + p;
            colG[k] = col0 + lc;
            nC[k] = njc[lc].x; lC[k] = __float_as_int(njc[lc].y);
        }

    float rp[8], rn[8], cpx[16], cn[16];
    #pragma unroll
    for (int k = 0; k < 8; k++)  { rp[k] = -1e30f; rn[k] = 1e30f; }
    #pragma unroll
    for (int k = 0; k < 16; k++) { cpx[k] = -1e30f; cn[k] = 1e30f; }

    #pragma unroll
    for (int ar = 0; ar < 4; ar++)
        #pragma unroll
        for (int na = 0; na < 8; na++)
            #pragma unroll
            for (int e = 0; e < 4; e++) {
                const int ri = ar * 2 + (e >> 1);
                const int ci = na * 2 + (e & 1);
                const float w  = -2.f * acc[ar][na][e];
                const float vr = w + nC[ci];
                const float vc = w + nR[ri];
                if (lR[ri] == lC[ci]) {
                    if (rowG[ri] != colG[ci]) {
                        rp[ri]  = fmaxf(rp[ri], vr);
                        cpx[ci] = fmaxf(cpx[ci], vc);
                    }
                } else {
                    rn[ri] = fminf(rn[ri], vr);
                    cn[ci] = fminf(cn[ci], vc);
                }
            }

    #pragma unroll
    for (int o = 1; o <= 2; o <<= 1)
        #pragma unroll
        for (int k = 0; k < 8; k++) {
            rp[k] = fmaxf(rp[k], __shfl_xor_sync(0xFFFFFFFFu, rp[k], o));
            rn[k] = fminf(rn[k], __shfl_xor_sync(0xFFFFFFFFu, rn[k], o));
        }
    #pragma unroll
    for (int o = 4; o <= 16; o <<= 1)
        #pragma unroll
        for (int k = 0; k < 16; k++) {
            cpx[k] = fmaxf(cpx[k], __shfl_xor_sync(0xFFFFFFFFu, cpx[k], o));
            cn[k]  = fminf(cn[k],  __shfl_xor_sync(0xFFFFFFFFu, cn[k], o));
        }

    if (qp == 0) {
        #pragma unroll
        for (int k = 0; k < 8; k++) {
            if (rp[k] > -1e29f) atomicMax(&g_v[rowG[k]].x, enc(rp[k]));
            if (rn[k] <  1e29f) atomicMin(&g_v[rowG[k]].y, enc(rn[k]));
        }
    }
    if (g == 0) {
        #pragma unroll
        for (int k = 0; k < 16; k++) {
            if (cpx[k] > -1e29f) atomicMax(&g_v[colG[k]].x, enc(cpx[k]));
            if (cn[k]  <  1e29f) atomicMin(&g_v[colG[k]].y, enc(cn[k]));
        }
    }
}

// ---------------- finalize ----------------
__global__ void finalize_kernel(float* out) {
    __shared__ float ss[32], sv[32];
    int tid = threadIdx.x;
    uint2 u[8]; float ni[8];
    #pragma unroll
    for (int k = 0; k < 8; k++) {
        u[k]  = g_v[tid + k * 1024];
        ni[k] = g_norms[tid + k * 1024];
    }
    float s = 0.f, v = 0.f;
    #pragma unroll
    for (int k = 0; k < 8; k++) {
        float vp = dec(u[k].x);
        float vn = dec(u[k].y);
        if (vp > -1e29f && vn < 1e29f) {
            float dp = sqrtf(fmaxf(vp + ni[k], 0.f));
            float dn = sqrtf(fmaxf(vn + ni[k], 0.f));
            s += fmaxf(dp - dn + MARGIN, 0.f);
            v += 1.f;
        }
    }
    #pragma unroll
    for (int o = 16; o; o >>= 1) {
        s += __shfl_xor_sync(0xFFFFFFFFu, s, o);
        v += __shfl_xor_sync(0xFFFFFFFFu, v, o);
    }
    int warp = tid >> 5, lane = tid & 31;
    if (lane == 0) { ss[warp] = s; sv[warp] = v; }
    __syncthreads();
    if (warp == 0) {
        s = ss[lane]; v = sv[lane];
        #pragma unroll
        for (int o = 16; o; o >>= 1) {
            s += __shfl_xor_sync(0xFFFFFFFFu, s, o);
            v += __shfl_xor_sync(0xFFFFFFFFu, v, o);
        }
        if (lane == 0) out[0] = (v > 0.f) ? (s / fmaxf(v, 1.f)) : 0.f;
    }
}

extern "C" void kernel_launch(void* const* d_in, const int* in_sizes, int n_in,
                              void* d_out, int out_size) {
    const float* E   = (const float*)d_in[0];
    const void*  lab = d_in[1];

    cudaFuncSetAttribute(mine_kernel, cudaFuncAttributeMaxDynamicSharedMemorySize, SMEM_TOTAL);

    prep_kernel<<<Bsz / 8, 256>>>(E, lab);
    mine_kernel<<<NGRID, 256, SMEM_TOTAL>>>();
    finalize_kernel<<<1, 1024>>>((float*)d_out);
}

// round 13
// speedup vs baseline: 16.2623x; 1.4048x over previous
#include <cuda_runtime.h>
#include <cuda_fp16.h>
#include <math.h>
#include <stdint.h>

#define Bsz    8192
#define Ddim   256
#define MARGIN 0.3f
#define NGRID  1056               // sum_{jt<32} (2*jt+2)

// ---- dynamic SMEM: 2 bufs x (A 16KB + B 32KB) + njr(1KB) + njc(2KB) ----
#define SM_BUF(b)   ((b) * 49152)
#define SM_A        0
#define SM_B        16384
#define SM_NJR      98304
#define SM_NJC      99328
#define SMEM_TOTAL  101376

__device__ float  g_norms[Bsz];
__device__ float2 g_njl[Bsz];
__device__ __half g_h[Bsz * Ddim];
__device__ uint2  g_v[Bsz];       // {enc(max pos v), enc(min neg v)}

__device__ __forceinline__ unsigned int enc(float f) {
    unsigned int u = __float_as_uint(f);
    return (u & 0x80000000u) ? ~u : (u | 0x80000000u);
}
__device__ __forceinline__ float dec(unsigned int u) {
    return (u & 0x80000000u) ? __uint_as_float(u ^ 0x80000000u) : __uint_as_float(~u);
}
__device__ __forceinline__ uint32_t smem_u32(const void* p) {
    uint32_t a;
    asm("{ .reg .u64 t; cvta.to.shared.u64 t, %1; cvt.u32.u64 %0, t; }" : "=r"(a) : "l"(p));
    return a;
}
__device__ __forceinline__ void cp_async16(uint32_t dst, const void* src) {
    asm volatile("cp.async.cg.shared.global [%0], [%1], 16;" :: "r"(dst), "l"(src) : "memory");
}
__device__ __forceinline__ void cp_commit() {
    asm volatile("cp.async.commit_group;" ::: "memory");
}
template <int N>
__device__ __forceinline__ void cp_wait() {
    asm volatile("cp.async.wait_group %0;" :: "n"(N) : "memory");
}
__device__ __forceinline__ void ldm_x4(uint32_t r[4], uint32_t addr) {
    asm volatile("ldmatrix.sync.aligned.m8n8.x4.shared.b16 {%0,%1,%2,%3}, [%4];"
                 : "=r"(r[0]), "=r"(r[1]), "=r"(r[2]), "=r"(r[3]) : "r"(addr));
}
__device__ __forceinline__ void mma16816(float d[4], const uint32_t a[4],
                                         uint32_t b0, uint32_t b1) {
    asm volatile(
        "mma.sync.aligned.m16n8k16.row.col.f32.f16.f16.f32 "
        "{%0,%1,%2,%3},{%4,%5,%6,%7},{%8,%9},{%0,%1,%2,%3};"
        : "+f"(d[0]), "+f"(d[1]), "+f"(d[2]), "+f"(d[3])
        : "r"(a[0]), "r"(a[1]), "r"(a[2]), "r"(a[3]), "r"(b0), "r"(b1));
}
__device__ __forceinline__ uint32_t swz(uint32_t off) {
    return off ^ ((off >> 3) & 0x70);
}

// ---------------- prep: fp16 pack + norms + njl + accumulator init ----------------
__global__ void prep_kernel(const float* __restrict__ E, const void* __restrict__ lab) {
    int warp = threadIdx.x >> 5, lane = threadIdx.x & 31;
    int row = blockIdx.x * 8 + warp;
    if (threadIdx.x < 8) {
        int idx = blockIdx.x * 8 + threadIdx.x;
        g_v[idx] = make_uint2(0u, 0xFFFFFFFFu);
    }
    const float4* e4 = (const float4*)(E + (size_t)row * Ddim);
    float4 v[2];
    v[0] = e4[lane * 2];
    v[1] = e4[lane * 2 + 1];
    float x[8] = {v[0].x, v[0].y, v[0].z, v[0].w, v[1].x, v[1].y, v[1].z, v[1].w};
    float s = 0.f;
    __half h[8];
    #pragma unroll
    for (int i = 0; i < 8; i++) {
        s += x[i] * x[i];
        h[i] = __float2half(x[i]);
    }
    *(uint4*)(g_h + (size_t)row * Ddim + lane * 8) = *(const uint4*)h;
    #pragma unroll
    for (int o = 16; o; o >>= 1) s += __shfl_xor_sync(0xFFFFFFFFu, s, o);
    if (lane == 0) {
        const int* li = (const int*)lab;
        int all0 = 1;
        #pragma unroll
        for (int i = 0; i < 32; i++)
            if (li[2 * i + 1] != 0) all0 = 0;
        int lb = all0 ? (int)((const long long*)lab)[row] : li[row];
        g_norms[row] = s;
        g_njl[row] = make_float2(s, __int_as_float(lb));
    }
}

// ---------------- main fused kernel ----------------
// CTA tile 128 rows x 256 cols; 8 warps, each 64x64. Single-pass fp16 MMA.
__global__ __launch_bounds__(256, 1) void mine_kernel() {
    extern __shared__ char smem[];
    const uint32_t sb = smem_u32(smem);
    const int tid  = threadIdx.x;
    const int wid  = tid >> 5;
    const int lane = tid & 31;
    const int wr   = wid & 1;          // 64-row group
    const int wc   = wid >> 1;         // 64-col group (0..3)

    // map blockIdx -> (jt, it) with it <= 2*jt+1
    int jt = 0, rem = blockIdx.x;
    while (rem >= 2 * jt + 2) { rem -= 2 * jt + 2; jt++; }
    const int it   = rem;
    const int row0 = it * 128;
    const int col0 = jt * 256;

    if (tid < 128) ((float2*)(smem + SM_NJR))[tid] = g_njl[row0 + tid];
    ((float2*)(smem + SM_NJC))[tid] = g_njl[col0 + tid];

    // one 64-wide k-chunk: A(128r x 8seg) + B(256r x 8seg) = 3072 16B segs; 12/thread
    auto issue_chunk = [&](int kc, int b) {
        #pragma unroll
        for (int i = 0; i < 12; i++) {
            int u = i * 256 + tid;
            int s, grow;
            uint32_t arroff;
            if (u < 1024) { s = u;        grow = row0 + (s >> 3); arroff = SM_A; }
            else          { s = u - 1024; grow = col0 + (s >> 3); arroff = SM_B; }
            int r = s >> 3, q = s & 7;
            const void* src = g_h + (size_t)grow * Ddim + kc * 64 + q * 8;
            uint32_t dst = sb + SM_BUF(b) + arroff + swz((uint32_t)(r * 128 + q * 16));
            cp_async16(dst, src);
        }
        cp_commit();
    };

    float acc[4][8][4];
    #pragma unroll
    for (int ar = 0; ar < 4; ar++)
        #pragma unroll
        for (int na = 0; na < 8; na++)
            #pragma unroll
            for (int e = 0; e < 4; e++) acc[ar][na][e] = 0.f;

    const int Rb = wr * 64;
    const int Cb = wc * 64;
    const int seg = lane >> 3;
    const int l7  = lane & 7;
    const int a_radd = (seg & 1) * 8 + l7;
    const int a_koff = (seg >> 1) * 16;
    const int b_radd = (seg >> 1) * 8 + l7;
    const int b_koff = (seg & 1) * 16;

    issue_chunk(0, 0);
    #pragma unroll
    for (int kc = 0; kc < 4; kc++) {
        const int b = kc & 1;
        if (kc < 3) { issue_chunk(kc + 1, b ^ 1); cp_wait<1>(); }
        else        { cp_wait<0>(); }
        __syncthreads();

        #pragma unroll
        for (int ks = 0; ks < 4; ks++) {
            uint32_t ah[4][4], bh[4][4];
            #pragma unroll
            for (int ar = 0; ar < 4; ar++) {
                uint32_t off = swz((uint32_t)((Rb + ar * 16 + a_radd) * 128 + ks * 32 + a_koff));
                ldm_x4(ah[ar], sb + SM_BUF(b) + SM_A + off);
            }
            #pragma unroll
            for (int i = 0; i < 4; i++) {
                uint32_t off = swz((uint32_t)((Cb + i * 16 + b_radd) * 128 + ks * 32 + b_koff));
                ldm_x4(bh[i], sb + SM_BUF(b) + SM_B + off);
            }
            #pragma unroll
            for (int ar = 0; ar < 4; ar++)
                #pragma unroll
                for (int na = 0; na < 8; na++) {
                    const int i = na >> 1, sel = (na & 1) * 2;
                    mma16816(acc[ar][na], ah[ar], bh[i][sel], bh[i][sel + 1]);
                }
        }
        __syncthreads();
    }

    // ---- epilogue: dual-direction batch-hard fold ----
    const int g  = lane >> 2;
    const int qp = lane & 3;

    int   rowG[8];  float nR[8];  int lR[8];
    int   colG[16]; float nC[16]; int lC[16];
    const float2* njr = (const float2*)(smem + SM_NJR);
    const float2* njc = (const float2*)(smem + SM_NJC);
    #pragma unroll
    for (int ar = 0; ar < 4; ar++)
        #pragma unroll
        for (int h = 0; h < 2; h++) {
            int lr = Rb + ar * 16 + g + h * 8;
            int k = ar * 2 + h;
            rowG[k] = row0 + lr;
            nR[k] = njr[lr].x; lR[k] = __float_as_int(njr[lr].y);
        }
    #pragma unroll
    for (int na = 0; na < 8; na++)
        #pragma unroll
        for (int p = 0; p < 2; p++) {
            int lc = Cb + na * 8 + qp * 2 + p;
            int k = na * 2 + p;
            colG[k] = col0 + lc;
            nC[k] = njc[lc].x; lC[k] = __float_as_int(njc[lc].y);
        }

    float rp[8], rn[8], cpx[16], cn[16];
    #pragma unroll
    for (int k = 0; k < 8; k++)  { rp[k] = -1e30f; rn[k] = 1e30f; }
    #pragma unroll
    for (int k = 0; k < 16; k++) { cpx[k] = -1e30f; cn[k] = 1e30f; }

    #pragma unroll
    for (int ar = 0; ar < 4; ar++)
        #pragma unroll
        for (int na = 0; na < 8; na++)
            #pragma unroll
            for (int e = 0; e < 4; e++) {
                const int ri = ar * 2 + (e >> 1);
                const int ci = na * 2 + (e & 1);
                const float w  = -2.f * acc[ar][na][e];
                const float vr = w + nC[ci];
                const float vc = w + nR[ri];
                if (lR[ri] == lC[ci]) {
                    if (rowG[ri] != colG[ci]) {
                        rp[ri]  = fmaxf(rp[ri], vr);
                        cpx[ci] = fmaxf(cpx[ci], vc);
                    }
                } else {
                    rn[ri] = fminf(rn[ri], vr);
                    cn[ci] = fminf(cn[ci], vc);
                }
            }

    #pragma unroll
    for (int o = 1; o <= 2; o <<= 1)
        #pragma unroll
        for (int k = 0; k < 8; k++) {
            rp[k] = fmaxf(rp[k], __shfl_xor_sync(0xFFFFFFFFu, rp[k], o));
            rn[k] = fminf(rn[k], __shfl_xor_sync(0xFFFFFFFFu, rn[k], o));
        }
    #pragma unroll
    for (int o = 4; o <= 16; o <<= 1)
        #pragma unroll
        for (int k = 0; k < 16; k++) {
            cpx[k] = fmaxf(cpx[k], __shfl_xor_sync(0xFFFFFFFFu, cpx[k], o));
            cn[k]  = fminf(cn[k],  __shfl_xor_sync(0xFFFFFFFFu, cn[k], o));
        }

    if (qp == 0) {
        #pragma unroll
        for (int k = 0; k < 8; k++) {
            if (rp[k] > -1e29f) atomicMax(&g_v[rowG[k]].x, enc(rp[k]));
            if (rn[k] <  1e29f) atomicMin(&g_v[rowG[k]].y, enc(rn[k]));
        }
    }
    if (g == 0) {
        #pragma unroll
        for (int k = 0; k < 16; k++) {
            if (cpx[k] > -1e29f) atomicMax(&g_v[colG[k]].x, enc(cpx[k]));
            if (cn[k]  <  1e29f) atomicMin(&g_v[colG[k]].y, enc(cn[k]));
        }
    }
}

// ---------------- finalize ----------------
__global__ void finalize_kernel(float* out) {
    __shared__ float ss[32], sv[32];
    int tid = threadIdx.x;
    uint2 u[8]; float ni[8];
    #pragma unroll
    for (int k = 0; k < 8; k++) {
        u[k]  = g_v[tid + k * 1024];
        ni[k] = g_norms[tid + k * 1024];
    }
    float s = 0.f, v = 0.f;
    #pragma unroll
    for (int k = 0; k < 8; k++) {
        float vp = dec(u[k].x);
        float vn = dec(u[k].y);
        if (vp > -1e29f && vn < 1e29f) {
            float dp = sqrtf(fmaxf(vp + ni[k], 0.f));
            float dn = sqrtf(fmaxf(vn + ni[k], 0.f));
            s += fmaxf(dp - dn + MARGIN, 0.f);
            v += 1.f;
        }
    }
    #pragma unroll
    for (int o = 16; o; o >>= 1) {
        s += __shfl_xor_sync(0xFFFFFFFFu, s, o);
        v += __shfl_xor_sync(0xFFFFFFFFu, v, o);
    }
    int warp = tid >> 5, lane = tid & 31;
    if (lane == 0) { ss[warp] = s; sv[warp] = v; }
    __syncthreads();
    if (warp == 0) {
        s = ss[lane]; v = sv[lane];
        #pragma unroll
        for (int o = 16; o; o >>= 1) {
            s += __shfl_xor_sync(0xFFFFFFFFu, s, o);
            v += __shfl_xor_sync(0xFFFFFFFFu, v, o);
        }
        if (lane == 0) out[0] = (v > 0.f) ? (s / fmaxf(v, 1.f)) : 0.f;
    }
}

extern "C" void kernel_launch(void* const* d_in, const int* in_sizes, int n_in,
                              void* d_out, int out_size) {
    const float* E   = (const float*)d_in[0];
    const void*  lab = d_in[1];

    cudaFuncSetAttribute(mine_kernel, cudaFuncAttributeMaxDynamicSharedMemorySize, SMEM_TOTAL);

    prep_kernel<<<Bsz / 8, 256>>>(E, lab);
    mine_kernel<<<NGRID, 256, SMEM_TOTAL>>>();
    finalize_kernel<<<1, 1024>>>((float*)d_out);
}